// round 1
// baseline (speedup 1.0000x reference)
#include <cuda_runtime.h>
#include <math.h>

#define BATCH 8
#define SEQ 512
#define BT (BATCH*SEQ)        // 4096
#define EMB 768
#define NH 12
#define DH 64
#define VOC 60
#define DST 128
#define NLAYER 12
#define QKVN (3*EMB)          // 2304
#define FFN (4*EMB)           // 3072

// ---------------- scratch (device globals; no allocation allowed) ----------
__device__ float g_h[BT*EMB];
__device__ float g_ln[BT*EMB];
__device__ float g_qkv[BT*QKVN];
__device__ float g_att[BT*EMB];
__device__ float g_mid[BT*FFN];
__device__ float g_scores[(size_t)BATCH*NH*SEQ*SEQ];   // 100.7 MB
__device__ float g_semb[VOC*EMB];
__device__ int   g_pre[BT];

// ---------------- reductions ----------------
__device__ __forceinline__ float breduce_sum(float v, float* sh, int nthr) {
#pragma unroll
    for (int o = 16; o > 0; o >>= 1) v += __shfl_xor_sync(0xffffffffu, v, o);
    int lane = threadIdx.x & 31, w = threadIdx.x >> 5;
    if (lane == 0) sh[w] = v;
    __syncthreads();
    float r = 0.f;
    if ((int)threadIdx.x < (nthr >> 5)) r = sh[threadIdx.x];
    if (threadIdx.x < 32) {
#pragma unroll
        for (int o = 16; o > 0; o >>= 1) r += __shfl_xor_sync(0xffffffffu, r, o);
        if (threadIdx.x == 0) sh[0] = r;
    }
    __syncthreads();
    r = sh[0];
    __syncthreads();
    return r;
}

__device__ __forceinline__ float breduce_max(float v, float* sh, int nthr) {
#pragma unroll
    for (int o = 16; o > 0; o >>= 1) v = fmaxf(v, __shfl_xor_sync(0xffffffffu, v, o));
    int lane = threadIdx.x & 31, w = threadIdx.x >> 5;
    if (lane == 0) sh[w] = v;
    __syncthreads();
    float r = -3.0e38f;
    if ((int)threadIdx.x < (nthr >> 5)) r = sh[threadIdx.x];
    if (threadIdx.x < 32) {
#pragma unroll
        for (int o = 16; o > 0; o >>= 1) r = fmaxf(r, __shfl_xor_sync(0xffffffffu, r, o));
        if (threadIdx.x == 0) sh[0] = r;
    }
    __syncthreads();
    r = sh[0];
    __syncthreads();
    return r;
}

// ---------------- automaton state scan (LDS-resident) ----------------
__global__ void state_scan_kernel(const int* __restrict__ ids, const int* __restrict__ mul) {
    __shared__ int smul[VOC*VOC];   // 14.4 KB
    __shared__ int sids[BT];        // 16 KB
    int tid = threadIdx.x;
    for (int i = tid; i < VOC*VOC; i += blockDim.x) smul[i] = mul[i];
    for (int i = tid; i < BT; i += blockDim.x) sids[i] = ids[i];
    __syncthreads();
    if (tid < BATCH) {
        int s = 0;  // ID_ID
        const int* row = sids + tid * SEQ;
        int* pre = g_pre + tid * SEQ;
        for (int t = 0; t < SEQ; t++) {
            pre[t] = s;
            s = smul[row[t] * VOC + s];
        }
    }
}

// g_semb[v, :] = state_emb[v, :] @ state_proj_w + state_proj_b
__global__ void state_proj_kernel(const float* __restrict__ semb,
                                  const float* __restrict__ W,
                                  const float* __restrict__ b) {
    int idx = blockIdx.x * blockDim.x + threadIdx.x;
    if (idx >= VOC * EMB) return;
    int v = idx / EMB, e = idx % EMB;
    float acc = b[e];
#pragma unroll 8
    for (int d = 0; d < DST; d++) acc += semb[v * DST + d] * W[d * EMB + e];
    g_semb[idx] = acc;
}

__global__ void embed_kernel(const int* __restrict__ ids,
                             const float* __restrict__ tok_emb,
                             const float* __restrict__ wpe) {
    int idx = blockIdx.x * blockDim.x + threadIdx.x;
    if (idx >= BT * EMB) return;
    int bt = idx / EMB, e = idx % EMB;
    int t = bt % SEQ;
    g_h[idx] = tok_emb[ids[bt] * EMB + e] + g_semb[g_pre[bt] * EMB + e] + wpe[t * EMB + e];
}

// ---------------- layernorm ----------------
__global__ __launch_bounds__(256) void ln_kernel(const float* __restrict__ x,
                                                 const float* __restrict__ g,
                                                 const float* __restrict__ b,
                                                 float* __restrict__ y) {
    __shared__ float sh[8];
    int row = blockIdx.x, tid = threadIdx.x;
    const float* xr = x + (size_t)row * EMB;
    float v0 = xr[tid], v1 = xr[tid + 256], v2 = xr[tid + 512];
    float mean = breduce_sum(v0 + v1 + v2, sh, 256) * (1.f / EMB);
    float d0 = v0 - mean, d1 = v1 - mean, d2 = v2 - mean;
    float var = breduce_sum(d0*d0 + d1*d1 + d2*d2, sh, 256) * (1.f / EMB);
    float rstd = rsqrtf(var + 1e-5f);
    float* yr = y + (size_t)row * EMB;
    yr[tid]       = d0 * rstd * g[tid]       + b[tid];
    yr[tid + 256] = d1 * rstd * g[tid + 256] + b[tid + 256];
    yr[tid + 512] = d2 * rstd * g[tid + 512] + b[tid + 512];
}

// ---------------- generic tiled GEMM: C = act(A@B + bias) (+ residual) -----
__device__ __forceinline__ float gelu_f(float x) {
    return 0.5f * x * (1.f + tanhf(0.7978845608028654f * (x + 0.044715f * x * x * x)));
}

template<bool GELU, bool RESID>
__global__ __launch_bounds__(256) void gemm_kernel(
    const float* __restrict__ A, int lda,
    const float* __restrict__ Bm, int ldb,
    const float* __restrict__ bias,
    const float* __restrict__ Res,
    float* __restrict__ C, int ldc,
    int M, int N, int K)
{
    __shared__ float As[16][68];  // padded; 272B rows keep float4 reads aligned
    __shared__ float Bs[16][64];
    int m0 = blockIdx.y * 64, n0 = blockIdx.x * 64;
    int tid = threadIdx.x;
    int tx = tid & 15, ty = tid >> 4;
    float acc[4][4] = {};
    for (int k0 = 0; k0 < K; k0 += 16) {
#pragma unroll
        for (int i = 0; i < 4; i++) {
            int lin = tid + i * 256;
            int r = lin >> 4, c = lin & 15;
            As[c][r] = A[(size_t)(m0 + r) * lda + k0 + c];
        }
#pragma unroll
        for (int i = 0; i < 4; i++) {
            int lin = tid + i * 256;
            int r = lin >> 6, c = lin & 63;
            int n = n0 + c;
            Bs[r][c] = (n < N) ? Bm[(size_t)(k0 + r) * ldb + n] : 0.f;
        }
        __syncthreads();
#pragma unroll
        for (int kk = 0; kk < 16; kk++) {
            float4 a4 = *reinterpret_cast<const float4*>(&As[kk][ty * 4]);
            float4 b4 = *reinterpret_cast<const float4*>(&Bs[kk][tx * 4]);
            float a[4] = {a4.x, a4.y, a4.z, a4.w};
            float bv[4] = {b4.x, b4.y, b4.z, b4.w};
#pragma unroll
            for (int i = 0; i < 4; i++)
#pragma unroll
                for (int j = 0; j < 4; j++)
                    acc[i][j] = fmaf(a[i], bv[j], acc[i][j]);
        }
        __syncthreads();
    }
#pragma unroll
    for (int i = 0; i < 4; i++) {
        int m = m0 + ty * 4 + i;
#pragma unroll
        for (int j = 0; j < 4; j++) {
            int n = n0 + tx * 4 + j;
            if (n < N) {
                float v = acc[i][j] + bias[n];
                if (GELU) v = gelu_f(v);
                if (RESID) v += Res[(size_t)m * ldc + n];
                C[(size_t)m * ldc + n] = v;
            }
        }
    }
}

// ---------------- attention: S = scale * Q @ K^T (lower-triangle tiles) ----
__global__ __launch_bounds__(256) void attn_scores_kernel() {
    int bh = blockIdx.z;
    int b = bh / NH, h = bh % NH;
    int t0 = blockIdx.y * 64, s0 = blockIdx.x * 64;
    if (s0 > t0 + 63) return;   // fully masked tile
    const float* qb = g_qkv + (size_t)b * SEQ * QKVN + h * DH;
    const float* kb = g_qkv + (size_t)b * SEQ * QKVN + EMB + h * DH;
    float* Sb = g_scores + (size_t)bh * SEQ * SEQ;
    __shared__ float Qs[64][65];  // [d][t]
    __shared__ float Ks[64][65];  // [d][s]
    int tid = threadIdx.x;
    int tx = tid & 15, ty = tid >> 4;
#pragma unroll
    for (int i = 0; i < 16; i++) {
        int lin = tid + i * 256;
        int r = lin >> 6, c = lin & 63;
        Qs[c][r] = qb[(size_t)(t0 + r) * QKVN + c];
        Ks[c][r] = kb[(size_t)(s0 + r) * QKVN + c];
    }
    __syncthreads();
    float acc[4][4] = {};
#pragma unroll 8
    for (int kk = 0; kk < 64; kk++) {
        float a[4], bv[4];
#pragma unroll
        for (int i = 0; i < 4; i++) a[i] = Qs[kk][ty * 4 + i];
#pragma unroll
        for (int j = 0; j < 4; j++) bv[j] = Ks[kk][tx * 4 + j];
#pragma unroll
        for (int i = 0; i < 4; i++)
#pragma unroll
            for (int j = 0; j < 4; j++)
                acc[i][j] = fmaf(a[i], bv[j], acc[i][j]);
    }
    const float scale = 0.125f;  // 1/sqrt(64)
#pragma unroll
    for (int i = 0; i < 4; i++) {
        int t = t0 + ty * 4 + i;
#pragma unroll
        for (int j = 0; j < 4; j++) {
            int s = s0 + tx * 4 + j;
            Sb[(size_t)t * SEQ + s] = acc[i][j] * scale;  // s>t garbage, never read
        }
    }
}

// softmax over s<=t; zero-fill only up to the next 64-boundary (PV reads that far)
__global__ __launch_bounds__(128) void softmax_kernel() {
    __shared__ float sh[4];
    int r = blockIdx.x;          // bh*SEQ + t
    int t = r & (SEQ - 1);
    float* row = g_scores + (size_t)r * SEQ;
    int n = t + 1;
    int tid = threadIdx.x;
    float mx = -3.0e38f;
    for (int i = tid; i < n; i += 128) mx = fmaxf(mx, row[i]);
    mx = breduce_max(mx, sh, 128);
    float sum = 0.f;
    for (int i = tid; i < n; i += 128) {
        float e = __expf(row[i] - mx);
        row[i] = e;
        sum += e;
    }
    sum = breduce_sum(sum, sh, 128);
    float inv = 1.f / sum;
    for (int i = tid; i < n; i += 128) row[i] *= inv;
    int zend = ((t >> 6) + 1) << 6;
    for (int i = n + tid; i < zend; i += 128) row[i] = 0.f;
}

// O[t, h*64+e] = sum_s P[t,s] * V[s,e]
__global__ __launch_bounds__(256) void attn_pv_kernel() {
    int bh = blockIdx.z;
    int b = bh / NH, h = bh % NH;
    int t0 = blockIdx.y * 64;
    const float* Pb = g_scores + (size_t)bh * SEQ * SEQ;
    const float* vb = g_qkv + (size_t)b * SEQ * QKVN + 2 * EMB + h * DH;
    __shared__ float Ps[16][68];
    __shared__ float Vs[16][64];
    int tid = threadIdx.x;
    int tx = tid & 15, ty = tid >> 4;
    float acc[4][4] = {};
    int kend = t0 + 64;  // P rows in this tile are zero beyond t0+63
    for (int k0 = 0; k0 < kend; k0 += 16) {
#pragma unroll
        for (int i = 0; i < 4; i++) {
            int lin = tid + i * 256;
            int r = lin >> 4, c = lin & 15;
            Ps[c][r] = Pb[(size_t)(t0 + r) * SEQ + k0 + c];
        }
#pragma unroll
        for (int i = 0; i < 4; i++) {
            int lin = tid + i * 256;
            int r = lin >> 6, c = lin & 63;
            Vs[r][c] = vb[(size_t)(k0 + r) * QKVN + c];
        }
        __syncthreads();
#pragma unroll
        for (int kk = 0; kk < 16; kk++) {
            float4 a4 = *reinterpret_cast<const float4*>(&Ps[kk][ty * 4]);
            float4 b4 = *reinterpret_cast<const float4*>(&Vs[kk][tx * 4]);
            float a[4] = {a4.x, a4.y, a4.z, a4.w};
            float bv[4] = {b4.x, b4.y, b4.z, b4.w};
#pragma unroll
            for (int i = 0; i < 4; i++)
#pragma unroll
                for (int j = 0; j < 4; j++)
                    acc[i][j] = fmaf(a[i], bv[j], acc[i][j]);
        }
        __syncthreads();
    }
#pragma unroll
    for (int i = 0; i < 4; i++) {
        int t = t0 + ty * 4 + i;
#pragma unroll
        for (int j = 0; j < 4; j++) {
            int e = tx * 4 + j;
            g_att[(size_t)(b * SEQ + t) * EMB + h * DH + e] = acc[i][j];
        }
    }
}

// ---------------- host orchestration ----------------
static void launch_gemm(const float* A, int lda, const float* Bm, int ldb,
                        const float* bias, const float* Res,
                        float* C, int ldc, int M, int N, int K,
                        bool gelu) {
    dim3 grid((N + 63) / 64, M / 64);
    if (gelu) {
        gemm_kernel<true, false><<<grid, 256>>>(A, lda, Bm, ldb, bias, nullptr, C, ldc, M, N, K);
    } else if (Res) {
        gemm_kernel<false, true><<<grid, 256>>>(A, lda, Bm, ldb, bias, Res, C, ldc, M, N, K);
    } else {
        gemm_kernel<false, false><<<grid, 256>>>(A, lda, Bm, ldb, bias, nullptr, C, ldc, M, N, K);
    }
}

extern "C" void kernel_launch(void* const* d_in, const int* in_sizes, int n_in,
                              void* d_out, int out_size) {
    const int*   ids          = (const int*)d_in[0];
    const int*   mul          = (const int*)d_in[1];
    const float* tok_emb      = (const float*)d_in[2];
    const float* state_emb    = (const float*)d_in[3];
    const float* state_proj_w = (const float*)d_in[4];
    const float* state_proj_b = (const float*)d_in[5];
    const float* wpe          = (const float*)d_in[6];
    const float* ln1_g        = (const float*)d_in[7];
    const float* ln1_b        = (const float*)d_in[8];
    const float* attn_w       = (const float*)d_in[9];
    const float* attn_b       = (const float*)d_in[10];
    const float* attn_proj_w  = (const float*)d_in[11];
    const float* attn_proj_b  = (const float*)d_in[12];
    const float* ln2_g        = (const float*)d_in[13];
    const float* ln2_b        = (const float*)d_in[14];
    const float* fc_w         = (const float*)d_in[15];
    const float* fc_b         = (const float*)d_in[16];
    const float* mlp_proj_w   = (const float*)d_in[17];
    const float* mlp_proj_b   = (const float*)d_in[18];
    const float* lnf_g        = (const float*)d_in[19];
    const float* lnf_b        = (const float*)d_in[20];
    const float* head_w       = (const float*)d_in[21];
    const float* head_b       = (const float*)d_in[22];
    float* out = (float*)d_out;

    float *h, *lnbuf, *qkv, *att, *mid;
    cudaGetSymbolAddress((void**)&h,     g_h);
    cudaGetSymbolAddress((void**)&lnbuf, g_ln);
    cudaGetSymbolAddress((void**)&qkv,   g_qkv);
    cudaGetSymbolAddress((void**)&att,   g_att);
    cudaGetSymbolAddress((void**)&mid,   g_mid);

    state_scan_kernel<<<1, 256>>>(ids, mul);
    state_proj_kernel<<<(VOC * EMB + 255) / 256, 256>>>(state_emb, state_proj_w, state_proj_b);
    embed_kernel<<<(BT * EMB + 255) / 256, 256>>>(ids, tok_emb, wpe);

    for (int l = 0; l < NLAYER; l++) {
        ln_kernel<<<BT, 256>>>(h, ln1_g + l * EMB, ln1_b + l * EMB, lnbuf);
        launch_gemm(lnbuf, EMB, attn_w + (size_t)l * EMB * QKVN, QKVN,
                    attn_b + l * QKVN, nullptr, qkv, QKVN, BT, QKVN, EMB, false);
        attn_scores_kernel<<<dim3(8, 8, BATCH * NH), 256>>>();
        softmax_kernel<<<BATCH * NH * SEQ, 128>>>();
        attn_pv_kernel<<<dim3(1, 8, BATCH * NH), 256>>>();
        launch_gemm(att, EMB, attn_proj_w + (size_t)l * EMB * EMB, EMB,
                    attn_proj_b + l * EMB, h, h, EMB, BT, EMB, EMB, false);
        ln_kernel<<<BT, 256>>>(h, ln2_g + l * EMB, ln2_b + l * EMB, lnbuf);
        launch_gemm(lnbuf, EMB, fc_w + (size_t)l * EMB * FFN, FFN,
                    fc_b + l * FFN, nullptr, mid, FFN, BT, FFN, EMB, true);
        launch_gemm(mid, FFN, mlp_proj_w + (size_t)l * FFN * EMB, EMB,
                    mlp_proj_b + l * EMB, h, h, EMB, BT, EMB, FFN, false);
    }

    ln_kernel<<<BT, 256>>>(h, lnf_g, lnf_b, lnbuf);
    launch_gemm(lnbuf, EMB, head_w, VOC, head_b, nullptr, out, VOC, BT, VOC, EMB, false);
}

// round 3
// speedup vs baseline: 1.6493x; 1.6493x over previous
#include <cuda_runtime.h>
#include <cuda_bf16.h>
#include <math.h>
#include <stdint.h>

#define BATCH 8
#define SEQ 512
#define BT (BATCH*SEQ)        // 4096
#define EMB 768
#define NH 12
#define DH 64
#define VOC 60
#define DST 128
#define NLAYER 12
#define QKVN (3*EMB)          // 2304
#define FFN (4*EMB)           // 3072

// ---------------- scratch (device globals; no allocation allowed) ----------
__device__ float g_h[BT*EMB];
__device__ float g_ln[BT*EMB];
__device__ float g_qkv[BT*QKVN];
__device__ float g_att[BT*EMB];
__device__ float g_mid[BT*FFN];
__device__ float g_scores[(size_t)BATCH*NH*SEQ*SEQ];   // 100.7 MB
__device__ float g_semb[VOC*EMB];
__device__ int   g_pre[BT];

// ---------------- helpers ----------------
__device__ __forceinline__ uint32_t smem_u32(const void* p) {
    uint32_t a;
    asm("{ .reg .u64 t; cvta.to.shared.u64 t, %1; cvt.u32.u64 %0, t; }" : "=r"(a) : "l"(p));
    return a;
}

__device__ __forceinline__ void ldsm_x4(uint32_t* r, uint32_t addr) {
    asm volatile("ldmatrix.sync.aligned.m8n8.x4.shared.b16 {%0,%1,%2,%3}, [%4];"
        : "=r"(r[0]), "=r"(r[1]), "=r"(r[2]), "=r"(r[3]) : "r"(addr));
}

__device__ __forceinline__ void mma16816(float* c, const uint32_t* a, const uint32_t* b) {
    asm volatile("mma.sync.aligned.m16n8k16.row.col.f32.bf16.bf16.f32 "
        "{%0,%1,%2,%3}, {%4,%5,%6,%7}, {%8,%9}, {%0,%1,%2,%3};"
        : "+f"(c[0]), "+f"(c[1]), "+f"(c[2]), "+f"(c[3])
        : "r"(a[0]), "r"(a[1]), "r"(a[2]), "r"(a[3]), "r"(b[0]), "r"(b[1]));
}

__device__ __forceinline__ void cvt_split2(float x0, float x1, uint32_t& hi, uint32_t& lo) {
    __nv_bfloat16 h0 = __float2bfloat16_rn(x0);
    __nv_bfloat16 h1 = __float2bfloat16_rn(x1);
    __nv_bfloat16 l0 = __float2bfloat16_rn(x0 - __bfloat162float(h0));
    __nv_bfloat16 l1 = __float2bfloat16_rn(x1 - __bfloat162float(h1));
    __nv_bfloat162 H(h0, h1), L(l0, l1);
    hi = *(uint32_t*)&H;
    lo = *(uint32_t*)&L;
}

// ---------------- reductions ----------------
__device__ __forceinline__ float breduce_sum(float v, float* sh, int nthr) {
#pragma unroll
    for (int o = 16; o > 0; o >>= 1) v += __shfl_xor_sync(0xffffffffu, v, o);
    int lane = threadIdx.x & 31, w = threadIdx.x >> 5;
    if (lane == 0) sh[w] = v;
    __syncthreads();
    float r = 0.f;
    if ((int)threadIdx.x < (nthr >> 5)) r = sh[threadIdx.x];
    if (threadIdx.x < 32) {
#pragma unroll
        for (int o = 16; o > 0; o >>= 1) r += __shfl_xor_sync(0xffffffffu, r, o);
        if (threadIdx.x == 0) sh[0] = r;
    }
    __syncthreads();
    r = sh[0];
    __syncthreads();
    return r;
}

__device__ __forceinline__ float breduce_max(float v, float* sh, int nthr) {
#pragma unroll
    for (int o = 16; o > 0; o >>= 1) v = fmaxf(v, __shfl_xor_sync(0xffffffffu, v, o));
    int lane = threadIdx.x & 31, w = threadIdx.x >> 5;
    if (lane == 0) sh[w] = v;
    __syncthreads();
    float r = -3.0e38f;
    if ((int)threadIdx.x < (nthr >> 5)) r = sh[threadIdx.x];
    if (threadIdx.x < 32) {
#pragma unroll
        for (int o = 16; o > 0; o >>= 1) r = fmaxf(r, __shfl_xor_sync(0xffffffffu, r, o));
        if (threadIdx.x == 0) sh[0] = r;
    }
    __syncthreads();
    r = sh[0];
    __syncthreads();
    return r;
}

// ---------------- automaton state scan (LDS-resident) ----------------
__global__ void state_scan_kernel(const int* __restrict__ ids, const int* __restrict__ mul) {
    __shared__ int smul[VOC*VOC];
    __shared__ int sids[BT];
    int tid = threadIdx.x;
    for (int i = tid; i < VOC*VOC; i += blockDim.x) smul[i] = mul[i];
    for (int i = tid; i < BT; i += blockDim.x) sids[i] = ids[i];
    __syncthreads();
    if (tid < BATCH) {
        int s = 0;
        const int* row = sids + tid * SEQ;
        int* pre = g_pre + tid * SEQ;
        for (int t = 0; t < SEQ; t++) {
            pre[t] = s;
            s = smul[row[t] * VOC + s];
        }
    }
}

__global__ void state_proj_kernel(const float* __restrict__ semb,
                                  const float* __restrict__ W,
                                  const float* __restrict__ b) {
    int idx = blockIdx.x * blockDim.x + threadIdx.x;
    if (idx >= VOC * EMB) return;
    int v = idx / EMB, e = idx % EMB;
    float acc = b[e];
#pragma unroll 8
    for (int d = 0; d < DST; d++) acc += semb[v * DST + d] * W[d * EMB + e];
    g_semb[idx] = acc;
}

__global__ void embed_kernel(const int* __restrict__ ids,
                             const float* __restrict__ tok_emb,
                             const float* __restrict__ wpe) {
    int idx = blockIdx.x * blockDim.x + threadIdx.x;
    if (idx >= BT * EMB) return;
    int bt = idx / EMB, e = idx % EMB;
    int t = bt % SEQ;
    g_h[idx] = tok_emb[ids[bt] * EMB + e] + g_semb[g_pre[bt] * EMB + e] + wpe[t * EMB + e];
}

// ---------------- layernorm ----------------
__global__ __launch_bounds__(256) void ln_kernel(const float* __restrict__ x,
                                                 const float* __restrict__ g,
                                                 const float* __restrict__ b,
                                                 float* __restrict__ y) {
    __shared__ float sh[8];
    int row = blockIdx.x, tid = threadIdx.x;
    const float* xr = x + (size_t)row * EMB;
    float v0 = xr[tid], v1 = xr[tid + 256], v2 = xr[tid + 512];
    float mean = breduce_sum(v0 + v1 + v2, sh, 256) * (1.f / EMB);
    float d0 = v0 - mean, d1 = v1 - mean, d2 = v2 - mean;
    float var = breduce_sum(d0*d0 + d1*d1 + d2*d2, sh, 256) * (1.f / EMB);
    float rstd = rsqrtf(var + 1e-5f);
    float* yr = y + (size_t)row * EMB;
    yr[tid]       = d0 * rstd * g[tid]       + b[tid];
    yr[tid + 256] = d1 * rstd * g[tid + 256] + b[tid + 256];
    yr[tid + 512] = d2 * rstd * g[tid + 512] + b[tid + 512];
}

// ================= mma.sync bf16-split GEMM ================================
// C[4096, N] = act(A[4096, K] @ W[K, N] + bias) (+ Res)
// CTA 128x128, 8 warps in 4(M)x2(N), warp tile 32x64, K-chunk 32.
// A = Ah + Al, W = Wh + Wl (bf16); C ≈ Ah·Wh + Ah·Wl + Al·Wh.

__device__ __forceinline__ float gelu_f(float x) {
    return 0.5f * x * (1.f + tanhf(0.7978845608028654f * (x + 0.044715f * x * x * x)));
}

// smem rows padded to 80B: 8 consecutive rows hit 8 distinct 16B banks.
#define ROWB 80
#define SM_AH 0
#define SM_AL (128*ROWB)
#define SM_BH (2*128*ROWB)
#define SM_BL (3*128*ROWB)
#define SM_TOT (4*128*ROWB)   // 40960 B

template<bool GELU, bool RESID>
__global__ __launch_bounds__(256, 1) void mma_gemm(
    const float* __restrict__ A, int lda,
    const float* __restrict__ W, int ldb,   // W is [K, N] row-major
    const float* __restrict__ bias,
    const float* Res,
    float* C, int ldc,
    int K)
{
    __shared__ __align__(16) char sm[SM_TOT];
    uint32_t sb = smem_u32(sm);
    int tid = threadIdx.x;
    int wid = tid >> 5, lane = tid & 31;
    int wm = wid & 3, wn = wid >> 2;
    int m0 = blockIdx.y * 128, n0 = blockIdx.x * 128;

    // producer indices
    int ar = tid >> 1, ah = tid & 1;           // A: row, k-half(16 floats)
    int bn = tid >> 1, bh = tid & 1;           // B: n-row, k-half

    // ldmatrix lane addressing (within-tile)
    int a_row = lane & 15;
    int a_colb = ((lane >> 4) * 8) * 2;        // byte offset of col group
    int b_row = (lane & 7) + ((lane >> 4) & 1) * 8;   // n within 16-wide pair
    int b_colb = (((lane >> 3) & 1) * 8) * 2;

    float acc[2][8][4];
#pragma unroll
    for (int i = 0; i < 2; i++)
#pragma unroll
        for (int j = 0; j < 8; j++)
#pragma unroll
            for (int q = 0; q < 4; q++) acc[i][j][q] = 0.f;

    for (int k0 = 0; k0 < K; k0 += 32) {
        // ---- produce A (128 x 32) hi/lo ----
        {
            const float* Ap = A + (size_t)(m0 + ar) * lda + k0 + ah * 16;
            uint32_t aoff = (uint32_t)(ar * ROWB + ah * 32);
#pragma unroll
            for (int j = 0; j < 4; j++) {
                float4 v = *reinterpret_cast<const float4*>(Ap + 4 * j);
                uint32_t h0, l0, h1, l1;
                cvt_split2(v.x, v.y, h0, l0);
                cvt_split2(v.z, v.w, h1, l1);
                *(uint2*)(sm + SM_AH + aoff + 8 * j) = make_uint2(h0, h1);
                *(uint2*)(sm + SM_AL + aoff + 8 * j) = make_uint2(l0, l1);
            }
        }
        // ---- produce B^T (128 n x 32 k) hi/lo ----
        {
            const float* Wp = W + (size_t)(k0 + bh * 16) * ldb + n0 + bn;
            uint32_t boff = (uint32_t)(bn * ROWB + bh * 32);
#pragma unroll
            for (int j = 0; j < 16; j += 2) {
                float w0 = Wp[(size_t)j * ldb];
                float w1 = Wp[(size_t)(j + 1) * ldb];
                uint32_t h, l;
                cvt_split2(w0, w1, h, l);
                *(uint32_t*)(sm + SM_BH + boff + 2 * j) = h;
                *(uint32_t*)(sm + SM_BL + boff + 2 * j) = l;
            }
        }
        __syncthreads();

#pragma unroll
        for (int ks = 0; ks < 2; ks++) {
            uint32_t a_hi[2][4], a_lo[2][4];
#pragma unroll
            for (int mt = 0; mt < 2; mt++) {
                uint32_t off = (uint32_t)((wm * 32 + mt * 16 + a_row) * ROWB
                                          + ks * 32 + a_colb);
                ldsm_x4(a_hi[mt], sb + SM_AH + off);
                ldsm_x4(a_lo[mt], sb + SM_AL + off);
            }
            uint32_t b_hi[4][4], b_lo[4][4];   // [n-pair][b0,b1,b0',b1']
#pragma unroll
            for (int p = 0; p < 4; p++) {
                uint32_t off = (uint32_t)((wn * 64 + p * 16 + b_row) * ROWB
                                          + ks * 32 + b_colb);
                ldsm_x4(b_hi[p], sb + SM_BH + off);
                ldsm_x4(b_lo[p], sb + SM_BL + off);
            }
            // split-major order: 16 independent accumulators between reuses
#pragma unroll
            for (int mt = 0; mt < 2; mt++)
#pragma unroll
                for (int p = 0; p < 4; p++) {
                    mma16816(acc[mt][2*p],   a_hi[mt], &b_hi[p][0]);
                    mma16816(acc[mt][2*p+1], a_hi[mt], &b_hi[p][2]);
                }
#pragma unroll
            for (int mt = 0; mt < 2; mt++)
#pragma unroll
                for (int p = 0; p < 4; p++) {
                    mma16816(acc[mt][2*p],   a_hi[mt], &b_lo[p][0]);
                    mma16816(acc[mt][2*p+1], a_hi[mt], &b_lo[p][2]);
                }
#pragma unroll
            for (int mt = 0; mt < 2; mt++)
#pragma unroll
                for (int p = 0; p < 4; p++) {
                    mma16816(acc[mt][2*p],   a_lo[mt], &b_hi[p][0]);
                    mma16816(acc[mt][2*p+1], a_lo[mt], &b_hi[p][2]);
                }
        }
        __syncthreads();
    }

    // ---- epilogue ----
    int r0 = m0 + wm * 32 + (lane >> 2);
    int c0 = n0 + wn * 64 + (lane & 3) * 2;
#pragma unroll
    for (int mt = 0; mt < 2; mt++) {
#pragma unroll
        for (int nt = 0; nt < 8; nt++) {
            int r = r0 + mt * 16;
            int cc = c0 + nt * 8;
            float b0 = bias[cc], b1 = bias[cc + 1];
            float v0 = acc[mt][nt][0] + b0;
            float v1 = acc[mt][nt][1] + b1;
            float v2 = acc[mt][nt][2] + b0;
            float v3 = acc[mt][nt][3] + b1;
            if (GELU) {
                v0 = gelu_f(v0); v1 = gelu_f(v1);
                v2 = gelu_f(v2); v3 = gelu_f(v3);
            }
            if (RESID) {
                const float* rp0 = Res + (size_t)r * ldc + cc;
                const float* rp1 = Res + (size_t)(r + 8) * ldc + cc;
                v0 += rp0[0]; v1 += rp0[1];
                v2 += rp1[0]; v3 += rp1[1];
            }
            *reinterpret_cast<float2*>(C + (size_t)r * ldc + cc) = make_float2(v0, v1);
            *reinterpret_cast<float2*>(C + (size_t)(r + 8) * ldc + cc) = make_float2(v2, v3);
        }
    }
}

// ---------------- small FFMA GEMM kept for the head (N=60) -----------------
__global__ __launch_bounds__(256) void head_gemm_kernel(
    const float* __restrict__ A,
    const float* __restrict__ Bm,
    const float* __restrict__ bias,
    float* __restrict__ C,
    int N, int K)
{
    __shared__ float As[16][68];
    __shared__ float Bs[16][64];
    int m0 = blockIdx.y * 64, n0 = blockIdx.x * 64;
    int tid = threadIdx.x;
    int tx = tid & 15, ty = tid >> 4;
    float acc[4][4] = {};
    for (int k0 = 0; k0 < K; k0 += 16) {
#pragma unroll
        for (int i = 0; i < 4; i++) {
            int lin = tid + i * 256;
            int r = lin >> 4, c = lin & 15;
            As[c][r] = A[(size_t)(m0 + r) * K + k0 + c];
        }
#pragma unroll
        for (int i = 0; i < 4; i++) {
            int lin = tid + i * 256;
            int r = lin >> 6, c = lin & 63;
            int n = n0 + c;
            Bs[r][c] = (n < N) ? Bm[(size_t)(k0 + r) * N + n] : 0.f;
        }
        __syncthreads();
#pragma unroll
        for (int kk = 0; kk < 16; kk++) {
            float4 a4 = *reinterpret_cast<const float4*>(&As[kk][ty * 4]);
            float4 b4 = *reinterpret_cast<const float4*>(&Bs[kk][tx * 4]);
            float a[4] = {a4.x, a4.y, a4.z, a4.w};
            float bv[4] = {b4.x, b4.y, b4.z, b4.w};
#pragma unroll
            for (int i = 0; i < 4; i++)
#pragma unroll
                for (int j = 0; j < 4; j++)
                    acc[i][j] = fmaf(a[i], bv[j], acc[i][j]);
        }
        __syncthreads();
    }
#pragma unroll
    for (int i = 0; i < 4; i++) {
        int m = m0 + ty * 4 + i;
#pragma unroll
        for (int j = 0; j < 4; j++) {
            int n = n0 + tx * 4 + j;
            if (n < N) C[(size_t)m * N + n] = acc[i][j] + bias[n];
        }
    }
}

// ---------------- attention: S = scale * Q @ K^T (lower-triangle tiles) ----
__global__ __launch_bounds__(256) void attn_scores_kernel() {
    int bh = blockIdx.z;
    int b = bh / NH, h = bh % NH;
    int t0 = blockIdx.y * 64, s0 = blockIdx.x * 64;
    if (s0 > t0 + 63) return;
    const float* qb = g_qkv + (size_t)b * SEQ * QKVN + h * DH;
    const float* kb = g_qkv + (size_t)b * SEQ * QKVN + EMB + h * DH;
    float* Sb = g_scores + (size_t)bh * SEQ * SEQ;
    __shared__ float Qs[64][65];
    __shared__ float Ks[64][65];
    int tid = threadIdx.x;
    int tx = tid & 15, ty = tid >> 4;
#pragma unroll
    for (int i = 0; i < 16; i++) {
        int lin = tid + i * 256;
        int r = lin >> 6, c = lin & 63;
        Qs[c][r] = qb[(size_t)(t0 + r) * QKVN + c];
        Ks[c][r] = kb[(size_t)(s0 + r) * QKVN + c];
    }
    __syncthreads();
    float acc[4][4] = {};
#pragma unroll 8
    for (int kk = 0; kk < 64; kk++) {
        float a[4], bv[4];
#pragma unroll
        for (int i = 0; i < 4; i++) a[i] = Qs[kk][ty * 4 + i];
#pragma unroll
        for (int j = 0; j < 4; j++) bv[j] = Ks[kk][tx * 4 + j];
#pragma unroll
        for (int i = 0; i < 4; i++)
#pragma unroll
            for (int j = 0; j < 4; j++)
                acc[i][j] = fmaf(a[i], bv[j], acc[i][j]);
    }
    const float scale = 0.125f;
#pragma unroll
    for (int i = 0; i < 4; i++) {
        int t = t0 + ty * 4 + i;
#pragma unroll
        for (int j = 0; j < 4; j++) {
            int s = s0 + tx * 4 + j;
            Sb[(size_t)t * SEQ + s] = acc[i][j] * scale;
        }
    }
}

__global__ __launch_bounds__(128) void softmax_kernel() {
    __shared__ float sh[4];
    int r = blockIdx.x;
    int t = r & (SEQ - 1);
    float* row = g_scores + (size_t)r * SEQ;
    int n = t + 1;
    int tid = threadIdx.x;
    float mx = -3.0e38f;
    for (int i = tid; i < n; i += 128) mx = fmaxf(mx, row[i]);
    mx = breduce_max(mx, sh, 128);
    float sum = 0.f;
    for (int i = tid; i < n; i += 128) {
        float e = __expf(row[i] - mx);
        row[i] = e;
        sum += e;
    }
    sum = breduce_sum(sum, sh, 128);
    float inv = 1.f / sum;
    for (int i = tid; i < n; i += 128) row[i] *= inv;
    int zend = ((t >> 6) + 1) << 6;
    for (int i = n + tid; i < zend; i += 128) row[i] = 0.f;
}

__global__ __launch_bounds__(256) void attn_pv_kernel() {
    int bh = blockIdx.z;
    int b = bh / NH, h = bh % NH;
    int t0 = blockIdx.y * 64;
    const float* Pb = g_scores + (size_t)bh * SEQ * SEQ;
    const float* vb = g_qkv + (size_t)b * SEQ * QKVN + 2 * EMB + h * DH;
    __shared__ float Ps[16][68];
    __shared__ float Vs[16][64];
    int tid = threadIdx.x;
    int tx = tid & 15, ty = tid >> 4;
    float acc[4][4] = {};
    int kend = t0 + 64;
    for (int k0 = 0; k0 < kend; k0 += 16) {
#pragma unroll
        for (int i = 0; i < 4; i++) {
            int lin = tid + i * 256;
            int r = lin >> 4, c = lin & 15;
            Ps[c][r] = Pb[(size_t)(t0 + r) * SEQ + k0 + c];
        }
#pragma unroll
        for (int i = 0; i < 4; i++) {
            int lin = tid + i * 256;
            int r = lin >> 6, c = lin & 63;
            Vs[r][c] = vb[(size_t)(k0 + r) * QKVN + c];
        }
        __syncthreads();
#pragma unroll
        for (int kk = 0; kk < 16; kk++) {
            float4 a4 = *reinterpret_cast<const float4*>(&Ps[kk][ty * 4]);
            float4 b4 = *reinterpret_cast<const float4*>(&Vs[kk][tx * 4]);
            float a[4] = {a4.x, a4.y, a4.z, a4.w};
            float bv[4] = {b4.x, b4.y, b4.z, b4.w};
#pragma unroll
            for (int i = 0; i < 4; i++)
#pragma unroll
                for (int j = 0; j < 4; j++)
                    acc[i][j] = fmaf(a[i], bv[j], acc[i][j]);
        }
        __syncthreads();
    }
#pragma unroll
    for (int i = 0; i < 4; i++) {
        int t = t0 + ty * 4 + i;
#pragma unroll
        for (int j = 0; j < 4; j++) {
            int e = tx * 4 + j;
            g_att[(size_t)(b * SEQ + t) * EMB + h * DH + e] = acc[i][j];
        }
    }
}

// ---------------- host orchestration ----------------
static void mma_launch(const float* A, int lda, const float* W, int N,
                       const float* bias, const float* Res, float* C, int K,
                       bool gelu) {
    dim3 grid(N / 128, BT / 128);
    if (gelu) {
        mma_gemm<true, false><<<grid, 256>>>(A, lda, W, N, bias, nullptr, C, N, K);
    } else if (Res) {
        mma_gemm<false, true><<<grid, 256>>>(A, lda, W, N, bias, Res, C, N, K);
    } else {
        mma_gemm<false, false><<<grid, 256>>>(A, lda, W, N, bias, nullptr, C, N, K);
    }
}

extern "C" void kernel_launch(void* const* d_in, const int* in_sizes, int n_in,
                              void* d_out, int out_size) {
    const int*   ids          = (const int*)d_in[0];
    const int*   mul          = (const int*)d_in[1];
    const float* tok_emb      = (const float*)d_in[2];
    const float* state_emb    = (const float*)d_in[3];
    const float* state_proj_w = (const float*)d_in[4];
    const float* state_proj_b = (const float*)d_in[5];
    const float* wpe          = (const float*)d_in[6];
    const float* ln1_g        = (const float*)d_in[7];
    const float* ln1_b        = (const float*)d_in[8];
    const float* attn_w       = (const float*)d_in[9];
    const float* attn_b       = (const float*)d_in[10];
    const float* attn_proj_w  = (const float*)d_in[11];
    const float* attn_proj_b  = (const float*)d_in[12];
    const float* ln2_g        = (const float*)d_in[13];
    const float* ln2_b        = (const float*)d_in[14];
    const float* fc_w         = (const float*)d_in[15];
    const float* fc_b         = (const float*)d_in[16];
    const float* mlp_proj_w   = (const float*)d_in[17];
    const float* mlp_proj_b   = (const float*)d_in[18];
    const float* lnf_g        = (const float*)d_in[19];
    const float* lnf_b        = (const float*)d_in[20];
    const float* head_w       = (const float*)d_in[21];
    const float* head_b       = (const float*)d_in[22];
    float* out = (float*)d_out;

    float *h, *lnbuf, *qkv, *att, *mid;
    cudaGetSymbolAddress((void**)&h,     g_h);
    cudaGetSymbolAddress((void**)&lnbuf, g_ln);
    cudaGetSymbolAddress((void**)&qkv,   g_qkv);
    cudaGetSymbolAddress((void**)&att,   g_att);
    cudaGetSymbolAddress((void**)&mid,   g_mid);

    state_scan_kernel<<<1, 256>>>(ids, mul);
    state_proj_kernel<<<(VOC * EMB + 255) / 256, 256>>>(state_emb, state_proj_w, state_proj_b);
    embed_kernel<<<(BT * EMB + 255) / 256, 256>>>(ids, tok_emb, wpe);

    for (int l = 0; l < NLAYER; l++) {
        ln_kernel<<<BT, 256>>>(h, ln1_g + l * EMB, ln1_b + l * EMB, lnbuf);
        mma_launch(lnbuf, EMB, attn_w + (size_t)l * EMB * QKVN, QKVN,
                   attn_b + l * QKVN, nullptr, qkv, EMB, false);
        attn_scores_kernel<<<dim3(8, 8, BATCH * NH), 256>>>();
        softmax_kernel<<<BATCH * NH * SEQ, 128>>>();
        attn_pv_kernel<<<dim3(1, 8, BATCH * NH), 256>>>();
        mma_launch(att, EMB, attn_proj_w + (size_t)l * EMB * EMB, EMB,
                   attn_proj_b + l * EMB, h, h, EMB, false);
        ln_kernel<<<BT, 256>>>(h, ln2_g + l * EMB, ln2_b + l * EMB, lnbuf);
        mma_launch(lnbuf, EMB, fc_w + (size_t)l * EMB * FFN, FFN,
                   fc_b + l * FFN, nullptr, mid, EMB, true);
        mma_launch(mid, FFN, mlp_proj_w + (size_t)l * FFN * EMB, EMB,
                   mlp_proj_b + l * EMB, h, h, FFN, false);
    }

    ln_kernel<<<BT, 256>>>(h, lnf_g, lnf_b, lnbuf);
    head_gemm_kernel<<<dim3(1, BT / 64), 256>>>(lnbuf, head_w, head_b, out, VOC, EMB);
}

// round 4
// speedup vs baseline: 2.0423x; 1.2383x over previous
#include <cuda_runtime.h>
#include <cuda_bf16.h>
#include <math.h>
#include <stdint.h>

#define BATCH 8
#define SEQ 512
#define BT (BATCH*SEQ)        // 4096
#define EMB 768
#define NH 12
#define DH 64
#define VOC 60
#define DST 128
#define NLAYER 12
#define QKVN (3*EMB)          // 2304
#define FFN (4*EMB)           // 3072

// per-layer weight element counts ([N][K] layout) and type-major offsets
#define W_QKV (QKVN*EMB)              // 1769472
#define W_PROJ (EMB*EMB)              // 589824
#define W_FC (FFN*EMB)                // 2359296
#define W_MLP (EMB*FFN)               // 2359296
#define OFF_QKV 0
#define OFF_PROJ (12*W_QKV)
#define OFF_FC (OFF_PROJ + 12*W_PROJ)
#define OFF_MLP (OFF_FC + 12*W_FC)
#define W_TOTAL (OFF_MLP + 12*W_MLP)  // 84934656

// ---------------- scratch (device globals; no allocation allowed) ----------
__device__ float g_h[BT*EMB];
__device__ float g_ln[BT*EMB];                 // fp32, for lnf -> head
__device__ float g_qkv[BT*QKVN];
__device__ float g_scores[(size_t)BATCH*NH*SEQ*SEQ];
__device__ float g_semb[VOC*EMB];
__device__ int   g_pre[BT];

__device__ __nv_bfloat16 g_wh[W_TOTAL];        // weights hi, [N][K]
__device__ __nv_bfloat16 g_wl[W_TOTAL];        // weights lo
__device__ __nv_bfloat16 g_lnh[BT*EMB], g_lnl[BT*EMB];
__device__ __nv_bfloat16 g_atth[BT*EMB], g_attl[BT*EMB];
__device__ __nv_bfloat16 g_midh[BT*FFN], g_midl[BT*FFN];

// ---------------- helpers ----------------
__device__ __forceinline__ uint32_t smem_u32(const void* p) {
    uint32_t a;
    asm("{ .reg .u64 t; cvta.to.shared.u64 t, %1; cvt.u32.u64 %0, t; }" : "=r"(a) : "l"(p));
    return a;
}

__device__ __forceinline__ void ldsm_x4(uint32_t* r, uint32_t addr) {
    asm volatile("ldmatrix.sync.aligned.m8n8.x4.shared.b16 {%0,%1,%2,%3}, [%4];"
        : "=r"(r[0]), "=r"(r[1]), "=r"(r[2]), "=r"(r[3]) : "r"(addr));
}

__device__ __forceinline__ void mma16816(float* c, const uint32_t* a, const uint32_t* b) {
    asm volatile("mma.sync.aligned.m16n8k16.row.col.f32.bf16.bf16.f32 "
        "{%0,%1,%2,%3}, {%4,%5,%6,%7}, {%8,%9}, {%0,%1,%2,%3};"
        : "+f"(c[0]), "+f"(c[1]), "+f"(c[2]), "+f"(c[3])
        : "r"(a[0]), "r"(a[1]), "r"(a[2]), "r"(a[3]), "r"(b[0]), "r"(b[1]));
}

__device__ __forceinline__ void cp16(uint32_t dst, const void* src) {
    asm volatile("cp.async.cg.shared.global [%0], [%1], 16;" :: "r"(dst), "l"(src));
}
#define CP_COMMIT() asm volatile("cp.async.commit_group;" ::: "memory")
#define CP_WAIT(n)  asm volatile("cp.async.wait_group %0;" :: "n"(n) : "memory")

__device__ __forceinline__ void cvt_split2(float x0, float x1, uint32_t& hi, uint32_t& lo) {
    __nv_bfloat16 h0 = __float2bfloat16_rn(x0);
    __nv_bfloat16 h1 = __float2bfloat16_rn(x1);
    __nv_bfloat16 l0 = __float2bfloat16_rn(x0 - __bfloat162float(h0));
    __nv_bfloat16 l1 = __float2bfloat16_rn(x1 - __bfloat162float(h1));
    __nv_bfloat162 H(h0, h1), L(l0, l1);
    hi = *(uint32_t*)&H;
    lo = *(uint32_t*)&L;
}

// ---------------- reductions ----------------
__device__ __forceinline__ float breduce_sum(float v, float* sh, int nthr) {
#pragma unroll
    for (int o = 16; o > 0; o >>= 1) v += __shfl_xor_sync(0xffffffffu, v, o);
    int lane = threadIdx.x & 31, w = threadIdx.x >> 5;
    if (lane == 0) sh[w] = v;
    __syncthreads();
    float r = 0.f;
    if ((int)threadIdx.x < (nthr >> 5)) r = sh[threadIdx.x];
    if (threadIdx.x < 32) {
#pragma unroll
        for (int o = 16; o > 0; o >>= 1) r += __shfl_xor_sync(0xffffffffu, r, o);
        if (threadIdx.x == 0) sh[0] = r;
    }
    __syncthreads();
    r = sh[0];
    __syncthreads();
    return r;
}

__device__ __forceinline__ float breduce_max(float v, float* sh, int nthr) {
#pragma unroll
    for (int o = 16; o > 0; o >>= 1) v = fmaxf(v, __shfl_xor_sync(0xffffffffu, v, o));
    int lane = threadIdx.x & 31, w = threadIdx.x >> 5;
    if (lane == 0) sh[w] = v;
    __syncthreads();
    float r = -3.0e38f;
    if ((int)threadIdx.x < (nthr >> 5)) r = sh[threadIdx.x];
    if (threadIdx.x < 32) {
#pragma unroll
        for (int o = 16; o > 0; o >>= 1) r = fmaxf(r, __shfl_xor_sync(0xffffffffu, r, o));
        if (threadIdx.x == 0) sh[0] = r;
    }
    __syncthreads();
    r = sh[0];
    __syncthreads();
    return r;
}

// ---------------- automaton state scan (LDS-resident) ----------------
__global__ void state_scan_kernel(const int* __restrict__ ids, const int* __restrict__ mul) {
    __shared__ int smul[VOC*VOC];
    __shared__ int sids[BT];
    int tid = threadIdx.x;
    for (int i = tid; i < VOC*VOC; i += blockDim.x) smul[i] = mul[i];
    for (int i = tid; i < BT; i += blockDim.x) sids[i] = ids[i];
    __syncthreads();
    if (tid < BATCH) {
        int s = 0;
        const int* row = sids + tid * SEQ;
        int* pre = g_pre + tid * SEQ;
        for (int t = 0; t < SEQ; t++) {
            pre[t] = s;
            s = smul[row[t] * VOC + s];
        }
    }
}

__global__ void state_proj_kernel(const float* __restrict__ semb,
                                  const float* __restrict__ W,
                                  const float* __restrict__ b) {
    int idx = blockIdx.x * blockDim.x + threadIdx.x;
    if (idx >= VOC * EMB) return;
    int v = idx / EMB, e = idx % EMB;
    float acc = b[e];
#pragma unroll 8
    for (int d = 0; d < DST; d++) acc += semb[v * DST + d] * W[d * EMB + e];
    g_semb[idx] = acc;
}

__global__ void embed_kernel(const int* __restrict__ ids,
                             const float* __restrict__ tok_emb,
                             const float* __restrict__ wpe) {
    int idx = blockIdx.x * blockDim.x + threadIdx.x;
    if (idx >= BT * EMB) return;
    int bt = idx / EMB, e = idx % EMB;
    int t = bt % SEQ;
    g_h[idx] = tok_emb[ids[bt] * EMB + e] + g_semb[g_pre[bt] * EMB + e] + wpe[t * EMB + e];
}

// ---------------- weight convert: W[K][N] fp32 -> Hi/Lo [N][K] bf16 --------
__global__ __launch_bounds__(256) void wconv_kernel(
    const float* __restrict__ W, __nv_bfloat16* __restrict__ Hi,
    __nv_bfloat16* __restrict__ Lo, int K, int N)
{
    __shared__ float t[32][33];
    int l = blockIdx.z;
    const float* Wl = W + (size_t)l * K * N;
    __nv_bfloat16* Hl = Hi + (size_t)l * K * N;
    __nv_bfloat16* Ll = Lo + (size_t)l * K * N;
    int n0 = blockIdx.x * 32, k0 = blockIdx.y * 32;
    int tx = threadIdx.x & 31, ty = threadIdx.x >> 5;   // 32 x 8
#pragma unroll
    for (int j = 0; j < 4; j++)
        t[ty + 8 * j][tx] = Wl[(size_t)(k0 + ty + 8 * j) * N + n0 + tx];
    __syncthreads();
#pragma unroll
    for (int j = 0; j < 4; j++) {
        float v = t[tx][ty + 8 * j];
        __nv_bfloat16 h = __float2bfloat16_rn(v);
        __nv_bfloat16 lo = __float2bfloat16_rn(v - __bfloat162float(h));
        size_t o = (size_t)(n0 + ty + 8 * j) * K + k0 + tx;
        Hl[o] = h;
        Ll[o] = lo;
    }
}

// ---------------- layernorm: fp32 out (for lnf) -----------------------------
__global__ __launch_bounds__(256) void ln_kernel(const float* __restrict__ x,
                                                 const float* __restrict__ g,
                                                 const float* __restrict__ b,
                                                 float* __restrict__ y) {
    __shared__ float sh[8];
    int row = blockIdx.x, tid = threadIdx.x;
    const float* xr = x + (size_t)row * EMB;
    float v0 = xr[tid], v1 = xr[tid + 256], v2 = xr[tid + 512];
    float mean = breduce_sum(v0 + v1 + v2, sh, 256) * (1.f / EMB);
    float d0 = v0 - mean, d1 = v1 - mean, d2 = v2 - mean;
    float var = breduce_sum(d0*d0 + d1*d1 + d2*d2, sh, 256) * (1.f / EMB);
    float rstd = rsqrtf(var + 1e-5f);
    float* yr = y + (size_t)row * EMB;
    yr[tid]       = d0 * rstd * g[tid]       + b[tid];
    yr[tid + 256] = d1 * rstd * g[tid + 256] + b[tid + 256];
    yr[tid + 512] = d2 * rstd * g[tid + 512] + b[tid + 512];
}

// ---------------- layernorm: bf16 hi/lo out (feeds tensor-core GEMMs) ------
__global__ __launch_bounds__(256) void ln_bf16_kernel(const float* __restrict__ x,
                                                      const float* __restrict__ g,
                                                      const float* __restrict__ b,
                                                      __nv_bfloat16* __restrict__ yh,
                                                      __nv_bfloat16* __restrict__ yl) {
    __shared__ float sh[8];
    int row = blockIdx.x, tid = threadIdx.x;
    const float* xr = x + (size_t)row * EMB;
    float v0 = xr[tid], v1 = xr[tid + 256], v2 = xr[tid + 512];
    float mean = breduce_sum(v0 + v1 + v2, sh, 256) * (1.f / EMB);
    float d0 = v0 - mean, d1 = v1 - mean, d2 = v2 - mean;
    float var = breduce_sum(d0*d0 + d1*d1 + d2*d2, sh, 256) * (1.f / EMB);
    float rstd = rsqrtf(var + 1e-5f);
    size_t base = (size_t)row * EMB;
#pragma unroll
    for (int q = 0; q < 3; q++) {
        int e = tid + q * 256;
        float d = (q == 0) ? d0 : (q == 1) ? d1 : d2;
        float v = d * rstd * g[e] + b[e];
        __nv_bfloat16 h = __float2bfloat16_rn(v);
        yh[base + e] = h;
        yl[base + e] = __float2bfloat16_rn(v - __bfloat162float(h));
    }
}

// ================= mma.sync bf16-split GEMM (cp.async double-buffered) =====
// C[4096, N] = epi(Ah+Al @ (Bh+Bl)^T + bias)
// A: [M][K] bf16 hi/lo row-major; B: [N][K] bf16 hi/lo row-major.
// CTA 128x128, 8 warps 4(M)x2(N), K-chunk 32. 3 split MMAs (drop Al*Bl).

__device__ __forceinline__ float gelu_f(float x) {
    return 0.5f * x * (1.f + tanhf(0.7978845608028654f * (x + 0.044715f * x * x * x)));
}

#define ROWB 80
#define SM_AH 0
#define SM_AL 10240
#define SM_BH 20480
#define SM_BL 30720
#define BUFSZ 40960
#define GEMM_SMEM (2*BUFSZ)

// EPI: 0 = fp32 C=acc+bias; 1 = fp32 C=acc+bias+Res; 2 = bf16 split of gelu(acc+bias)
template<int EPI>
__global__ __launch_bounds__(256, 1) void mma_gemm(
    const __nv_bfloat16* __restrict__ Ah, const __nv_bfloat16* __restrict__ Al,
    const __nv_bfloat16* __restrict__ Bh, const __nv_bfloat16* __restrict__ Bl,
    const float* __restrict__ bias,
    const float* __restrict__ Res,
    float* __restrict__ C,
    __nv_bfloat16* __restrict__ Ch, __nv_bfloat16* __restrict__ Cl,
    int K, int N)
{
    extern __shared__ __align__(16) char sm[];
    uint32_t sb = smem_u32(sm);
    int tid = threadIdx.x;
    int wid = tid >> 5, lane = tid & 31;
    int wm = wid & 3, wn = wid >> 2;
    int m0 = blockIdx.y * 128, n0 = blockIdx.x * 128;

    // producer: each thread does 2 lin-slots x 4 regions of 16B cp.async
    int p_row = tid >> 2;         // lin>>2 for i=0; +64 for i=1
    int p_seg = tid & 3;

    // ldmatrix lane addressing
    int a_row = lane & 15;
    int a_colb = ((lane >> 4) * 8) * 2;
    int b_row = (lane & 7) + ((lane >> 4) & 1) * 8;
    int b_colb = (((lane >> 3) & 1) * 8) * 2;

    float acc[2][8][4];
#pragma unroll
    for (int i = 0; i < 2; i++)
#pragma unroll
        for (int j = 0; j < 8; j++)
#pragma unroll
            for (int q = 0; q < 4; q++) acc[i][j][q] = 0.f;

    const int nch = K >> 5;

    // --- issue chunk c into buffer bufsel ---
    auto issue = [&](int c, int bufsel) {
        int k0 = c << 5;
        uint32_t base = sb + bufsel * BUFSZ;
#pragma unroll
        for (int i = 0; i < 2; i++) {
            int row = p_row + i * 64;
            uint32_t doff = (uint32_t)(row * ROWB + p_seg * 16);
            size_t aoff = (size_t)(m0 + row) * K + k0 + p_seg * 8;
            size_t boff = (size_t)(n0 + row) * K + k0 + p_seg * 8;
            cp16(base + SM_AH + doff, Ah + aoff);
            cp16(base + SM_AL + doff, Al + aoff);
            cp16(base + SM_BH + doff, Bh + boff);
            cp16(base + SM_BL + doff, Bl + boff);
        }
    };

    issue(0, 0);
    CP_COMMIT();

    for (int c = 0; c < nch; c++) {
        int cur = c & 1;
        if (c + 1 < nch) {
            issue(c + 1, cur ^ 1);
            CP_COMMIT();
            CP_WAIT(1);
        } else {
            CP_WAIT(0);
        }
        __syncthreads();

        uint32_t base = sb + cur * BUFSZ;
#pragma unroll
        for (int ks = 0; ks < 2; ks++) {
            uint32_t a_hi[2][4], a_lo[2][4];
#pragma unroll
            for (int mt = 0; mt < 2; mt++) {
                uint32_t off = (uint32_t)((wm * 32 + mt * 16 + a_row) * ROWB
                                          + ks * 32 + a_colb);
                ldsm_x4(a_hi[mt], base + SM_AH + off);
                ldsm_x4(a_lo[mt], base + SM_AL + off);
            }
            uint32_t b_hi[4][4], b_lo[4][4];
#pragma unroll
            for (int p = 0; p < 4; p++) {
                uint32_t off = (uint32_t)((wn * 64 + p * 16 + b_row) * ROWB
                                          + ks * 32 + b_colb);
                ldsm_x4(b_hi[p], base + SM_BH + off);
                ldsm_x4(b_lo[p], base + SM_BL + off);
            }
#pragma unroll
            for (int mt = 0; mt < 2; mt++)
#pragma unroll
                for (int p = 0; p < 4; p++) {
                    mma16816(acc[mt][2*p],   a_hi[mt], &b_hi[p][0]);
                    mma16816(acc[mt][2*p+1], a_hi[mt], &b_hi[p][2]);
                }
#pragma unroll
            for (int mt = 0; mt < 2; mt++)
#pragma unroll
                for (int p = 0; p < 4; p++) {
                    mma16816(acc[mt][2*p],   a_hi[mt], &b_lo[p][0]);
                    mma16816(acc[mt][2*p+1], a_hi[mt], &b_lo[p][2]);
                }
#pragma unroll
            for (int mt = 0; mt < 2; mt++)
#pragma unroll
                for (int p = 0; p < 4; p++) {
                    mma16816(acc[mt][2*p],   a_lo[mt], &b_hi[p][0]);
                    mma16816(acc[mt][2*p+1], a_lo[mt], &b_hi[p][2]);
                }
        }
        __syncthreads();
    }

    // ---- epilogue ----
    int r0 = m0 + wm * 32 + (lane >> 2);
    int c0 = n0 + wn * 64 + (lane & 3) * 2;
#pragma unroll
    for (int mt = 0; mt < 2; mt++) {
#pragma unroll
        for (int nt = 0; nt < 8; nt++) {
            int r = r0 + mt * 16;
            int cc = c0 + nt * 8;
            float b0 = bias[cc], b1 = bias[cc + 1];
            float v0 = acc[mt][nt][0] + b0;
            float v1 = acc[mt][nt][1] + b1;
            float v2 = acc[mt][nt][2] + b0;
            float v3 = acc[mt][nt][3] + b1;
            if (EPI == 2) {
                v0 = gelu_f(v0); v1 = gelu_f(v1);
                v2 = gelu_f(v2); v3 = gelu_f(v3);
                uint32_t h01, l01, h23, l23;
                cvt_split2(v0, v1, h01, l01);
                cvt_split2(v2, v3, h23, l23);
                *(uint32_t*)(Ch + (size_t)r * N + cc) = h01;
                *(uint32_t*)(Cl + (size_t)r * N + cc) = l01;
                *(uint32_t*)(Ch + (size_t)(r + 8) * N + cc) = h23;
                *(uint32_t*)(Cl + (size_t)(r + 8) * N + cc) = l23;
            } else {
                if (EPI == 1) {
                    const float* rp0 = Res + (size_t)r * N + cc;
                    const float* rp1 = Res + (size_t)(r + 8) * N + cc;
                    v0 += rp0[0]; v1 += rp0[1];
                    v2 += rp1[0]; v3 += rp1[1];
                }
                *reinterpret_cast<float2*>(C + (size_t)r * N + cc) = make_float2(v0, v1);
                *reinterpret_cast<float2*>(C + (size_t)(r + 8) * N + cc) = make_float2(v2, v3);
            }
        }
    }
}

// ---------------- small FFMA GEMM kept for the head (N=60) -----------------
__global__ __launch_bounds__(256) void head_gemm_kernel(
    const float* __restrict__ A,
    const float* __restrict__ Bm,
    const float* __restrict__ bias,
    float* __restrict__ C,
    int N, int K)
{
    __shared__ float As[16][68];
    __shared__ float Bs[16][64];
    int m0 = blockIdx.y * 64, n0 = blockIdx.x * 64;
    int tid = threadIdx.x;
    int tx = tid & 15, ty = tid >> 4;
    float acc[4][4] = {};
    for (int k0 = 0; k0 < K; k0 += 16) {
#pragma unroll
        for (int i = 0; i < 4; i++) {
            int lin = tid + i * 256;
            int r = lin >> 4, c = lin & 15;
            As[c][r] = A[(size_t)(m0 + r) * K + k0 + c];
        }
#pragma unroll
        for (int i = 0; i < 4; i++) {
            int lin = tid + i * 256;
            int r = lin >> 6, c = lin & 63;
            int n = n0 + c;
            Bs[r][c] = (n < N) ? Bm[(size_t)(k0 + r) * N + n] : 0.f;
        }
        __syncthreads();
#pragma unroll
        for (int kk = 0; kk < 16; kk++) {
            float4 a4 = *reinterpret_cast<const float4*>(&As[kk][ty * 4]);
            float4 b4 = *reinterpret_cast<const float4*>(&Bs[kk][tx * 4]);
            float a[4] = {a4.x, a4.y, a4.z, a4.w};
            float bv[4] = {b4.x, b4.y, b4.z, b4.w};
#pragma unroll
            for (int i = 0; i < 4; i++)
#pragma unroll
                for (int j = 0; j < 4; j++)
                    acc[i][j] = fmaf(a[i], bv[j], acc[i][j]);
        }
        __syncthreads();
    }
#pragma unroll
    for (int i = 0; i < 4; i++) {
        int m = m0 + ty * 4 + i;
#pragma unroll
        for (int j = 0; j < 4; j++) {
            int n = n0 + tx * 4 + j;
            if (n < N) C[(size_t)m * N + n] = acc[i][j] + bias[n];
        }
    }
}

// ---------------- attention: S = scale * Q @ K^T (lower-triangle tiles) ----
__global__ __launch_bounds__(256) void attn_scores_kernel() {
    int bh = blockIdx.z;
    int b = bh / NH, h = bh % NH;
    int t0 = blockIdx.y * 64, s0 = blockIdx.x * 64;
    if (s0 > t0 + 63) return;
    const float* qb = g_qkv + (size_t)b * SEQ * QKVN + h * DH;
    const float* kb = g_qkv + (size_t)b * SEQ * QKVN + EMB + h * DH;
    float* Sb = g_scores + (size_t)bh * SEQ * SEQ;
    __shared__ float Qs[64][65];
    __shared__ float Ks[64][65];
    int tid = threadIdx.x;
    int tx = tid & 15, ty = tid >> 4;
#pragma unroll
    for (int i = 0; i < 16; i++) {
        int lin = tid + i * 256;
        int r = lin >> 6, c = lin & 63;
        Qs[c][r] = qb[(size_t)(t0 + r) * QKVN + c];
        Ks[c][r] = kb[(size_t)(s0 + r) * QKVN + c];
    }
    __syncthreads();
    float acc[4][4] = {};
#pragma unroll 8
    for (int kk = 0; kk < 64; kk++) {
        float a[4], bv[4];
#pragma unroll
        for (int i = 0; i < 4; i++) a[i] = Qs[kk][ty * 4 + i];
#pragma unroll
        for (int j = 0; j < 4; j++) bv[j] = Ks[kk][tx * 4 + j];
#pragma unroll
        for (int i = 0; i < 4; i++)
#pragma unroll
            for (int j = 0; j < 4; j++)
                acc[i][j] = fmaf(a[i], bv[j], acc[i][j]);
    }
    const float scale = 0.125f;
#pragma unroll
    for (int i = 0; i < 4; i++) {
        int t = t0 + ty * 4 + i;
#pragma unroll
        for (int j = 0; j < 4; j++) {
            int s = s0 + tx * 4 + j;
            Sb[(size_t)t * SEQ + s] = acc[i][j] * scale;
        }
    }
}

__global__ __launch_bounds__(128) void softmax_kernel() {
    __shared__ float sh[4];
    int r = blockIdx.x;
    int t = r & (SEQ - 1);
    float* row = g_scores + (size_t)r * SEQ;
    int n = t + 1;
    int tid = threadIdx.x;
    float mx = -3.0e38f;
    for (int i = tid; i < n; i += 128) mx = fmaxf(mx, row[i]);
    mx = breduce_max(mx, sh, 128);
    float sum = 0.f;
    for (int i = tid; i < n; i += 128) {
        float e = __expf(row[i] - mx);
        row[i] = e;
        sum += e;
    }
    sum = breduce_sum(sum, sh, 128);
    float inv = 1.f / sum;
    for (int i = tid; i < n; i += 128) row[i] *= inv;
    int zend = ((t >> 6) + 1) << 6;
    for (int i = n + tid; i < zend; i += 128) row[i] = 0.f;
}

// O written as bf16 hi/lo (feeds proj GEMM)
__global__ __launch_bounds__(256) void attn_pv_kernel() {
    int bh = blockIdx.z;
    int b = bh / NH, h = bh % NH;
    int t0 = blockIdx.y * 64;
    const float* Pb = g_scores + (size_t)bh * SEQ * SEQ;
    const float* vb = g_qkv + (size_t)b * SEQ * QKVN + 2 * EMB + h * DH;
    __shared__ float Ps[16][68];
    __shared__ float Vs[16][64];
    int tid = threadIdx.x;
    int tx = tid & 15, ty = tid >> 4;
    float acc[4][4] = {};
    int kend = t0 + 64;
    for (int k0 = 0; k0 < kend; k0 += 16) {
#pragma unroll
        for (int i = 0; i < 4; i++) {
            int lin = tid + i * 256;
            int r = lin >> 4, c = lin & 15;
            Ps[c][r] = Pb[(size_t)(t0 + r) * SEQ + k0 + c];
        }
#pragma unroll
        for (int i = 0; i < 4; i++) {
            int lin = tid + i * 256;
            int r = lin >> 6, c = lin & 63;
            Vs[r][c] = vb[(size_t)(k0 + r) * QKVN + c];
        }
        __syncthreads();
#pragma unroll
        for (int kk = 0; kk < 16; kk++) {
            float4 a4 = *reinterpret_cast<const float4*>(&Ps[kk][ty * 4]);
            float4 b4 = *reinterpret_cast<const float4*>(&Vs[kk][tx * 4]);
            float a[4] = {a4.x, a4.y, a4.z, a4.w};
            float bv[4] = {b4.x, b4.y, b4.z, b4.w};
#pragma unroll
            for (int i = 0; i < 4; i++)
#pragma unroll
                for (int j = 0; j < 4; j++)
                    acc[i][j] = fmaf(a[i], bv[j], acc[i][j]);
        }
        __syncthreads();
    }
#pragma unroll
    for (int i = 0; i < 4; i++) {
        int t = t0 + ty * 4 + i;
        size_t base = (size_t)(b * SEQ + t) * EMB + h * DH + tx * 4;
        uint32_t h01, l01, h23, l23;
        cvt_split2(acc[i][0], acc[i][1], h01, l01);
        cvt_split2(acc[i][2], acc[i][3], h23, l23);
        *(uint32_t*)(g_atth + base)     = h01;
        *(uint32_t*)(g_attl + base)     = l01;
        *(uint32_t*)(g_atth + base + 2) = h23;
        *(uint32_t*)(g_attl + base + 2) = l23;
    }
}

// ---------------- host orchestration ----------------
extern "C" void kernel_launch(void* const* d_in, const int* in_sizes, int n_in,
                              void* d_out, int out_size) {
    const int*   ids          = (const int*)d_in[0];
    const int*   mul          = (const int*)d_in[1];
    const float* tok_emb      = (const float*)d_in[2];
    const float* state_emb    = (const float*)d_in[3];
    const float* state_proj_w = (const float*)d_in[4];
    const float* state_proj_b = (const float*)d_in[5];
    const float* wpe          = (const float*)d_in[6];
    const float* ln1_g        = (const float*)d_in[7];
    const float* ln1_b        = (const float*)d_in[8];
    const float* attn_w       = (const float*)d_in[9];
    const float* attn_b       = (const float*)d_in[10];
    const float* attn_proj_w  = (const float*)d_in[11];
    const float* attn_proj_b  = (const float*)d_in[12];
    const float* ln2_g        = (const float*)d_in[13];
    const float* ln2_b        = (const float*)d_in[14];
    const float* fc_w         = (const float*)d_in[15];
    const float* fc_b         = (const float*)d_in[16];
    const float* mlp_proj_w   = (const float*)d_in[17];
    const float* mlp_proj_b   = (const float*)d_in[18];
    const float* lnf_g        = (const float*)d_in[19];
    const float* lnf_b        = (const float*)d_in[20];
    const float* head_w       = (const float*)d_in[21];
    const float* head_b       = (const float*)d_in[22];
    float* out = (float*)d_out;

    float *h, *lnbuf, *qkv;
    __nv_bfloat16 *wh, *wl, *lnh, *lnl, *atth, *attl, *midh, *midl;
    cudaGetSymbolAddress((void**)&h,     g_h);
    cudaGetSymbolAddress((void**)&lnbuf, g_ln);
    cudaGetSymbolAddress((void**)&qkv,   g_qkv);
    cudaGetSymbolAddress((void**)&wh,    g_wh);
    cudaGetSymbolAddress((void**)&wl,    g_wl);
    cudaGetSymbolAddress((void**)&lnh,   g_lnh);
    cudaGetSymbolAddress((void**)&lnl,   g_lnl);
    cudaGetSymbolAddress((void**)&atth,  g_atth);
    cudaGetSymbolAddress((void**)&attl,  g_attl);
    cudaGetSymbolAddress((void**)&midh,  g_midh);
    cudaGetSymbolAddress((void**)&midl,  g_midl);

    cudaFuncSetAttribute(mma_gemm<0>, cudaFuncAttributeMaxDynamicSharedMemorySize, GEMM_SMEM);
    cudaFuncSetAttribute(mma_gemm<1>, cudaFuncAttributeMaxDynamicSharedMemorySize, GEMM_SMEM);
    cudaFuncSetAttribute(mma_gemm<2>, cudaFuncAttributeMaxDynamicSharedMemorySize, GEMM_SMEM);

    // weight pre-conversion (all layers, transposed + split)
    wconv_kernel<<<dim3(QKVN/32, EMB/32, NLAYER), 256>>>(attn_w, wh + OFF_QKV, wl + OFF_QKV, EMB, QKVN);
    wconv_kernel<<<dim3(EMB/32, EMB/32, NLAYER), 256>>>(attn_proj_w, wh + OFF_PROJ, wl + OFF_PROJ, EMB, EMB);
    wconv_kernel<<<dim3(FFN/32, EMB/32, NLAYER), 256>>>(fc_w, wh + OFF_FC, wl + OFF_FC, EMB, FFN);
    wconv_kernel<<<dim3(EMB/32, FFN/32, NLAYER), 256>>>(mlp_proj_w, wh + OFF_MLP, wl + OFF_MLP, FFN, EMB);

    state_scan_kernel<<<1, 256>>>(ids, mul);
    state_proj_kernel<<<(VOC * EMB + 255) / 256, 256>>>(state_emb, state_proj_w, state_proj_b);
    embed_kernel<<<(BT * EMB + 255) / 256, 256>>>(ids, tok_emb, wpe);

    for (int l = 0; l < NLAYER; l++) {
        ln_bf16_kernel<<<BT, 256>>>(h, ln1_g + l * EMB, ln1_b + l * EMB, lnh, lnl);
        mma_gemm<0><<<dim3(QKVN/128, BT/128), 256, GEMM_SMEM>>>(
            lnh, lnl, wh + OFF_QKV + (size_t)l * W_QKV, wl + OFF_QKV + (size_t)l * W_QKV,
            attn_b + l * QKVN, nullptr, qkv, nullptr, nullptr, EMB, QKVN);
        attn_scores_kernel<<<dim3(8, 8, BATCH * NH), 256>>>();
        softmax_kernel<<<BATCH * NH * SEQ, 128>>>();
        attn_pv_kernel<<<dim3(1, 8, BATCH * NH), 256>>>();
        mma_gemm<1><<<dim3(EMB/128, BT/128), 256, GEMM_SMEM>>>(
            atth, attl, wh + OFF_PROJ + (size_t)l * W_PROJ, wl + OFF_PROJ + (size_t)l * W_PROJ,
            attn_proj_b + l * EMB, h, h, nullptr, nullptr, EMB, EMB);
        ln_bf16_kernel<<<BT, 256>>>(h, ln2_g + l * EMB, ln2_b + l * EMB, lnh, lnl);
        mma_gemm<2><<<dim3(FFN/128, BT/128), 256, GEMM_SMEM>>>(
            lnh, lnl, wh + OFF_FC + (size_t)l * W_FC, wl + OFF_FC + (size_t)l * W_FC,
            fc_b + l * FFN, nullptr, nullptr, midh, midl, EMB, FFN);
        mma_gemm<1><<<dim3(EMB/128, BT/128), 256, GEMM_SMEM>>>(
            midh, midl, wh + OFF_MLP + (size_t)l * W_MLP, wl + OFF_MLP + (size_t)l * W_MLP,
            mlp_proj_b + l * EMB, h, h, nullptr, nullptr, FFN, EMB);
    }

    ln_kernel<<<BT, 256>>>(h, lnf_g, lnf_b, lnbuf);
    head_gemm_kernel<<<dim3(1, BT / 64), 256>>>(lnbuf, head_w, head_b, out, VOC, EMB);
}

// round 5
// speedup vs baseline: 2.3579x; 1.1545x over previous
#include <cuda_runtime.h>
#include <cuda_bf16.h>
#include <math.h>
#include <stdint.h>

#define BATCH 8
#define SEQ 512
#define BT (BATCH*SEQ)        // 4096
#define EMB 768
#define NH 12
#define DH 64
#define VOC 60
#define DST 128
#define NLAYER 12
#define QKVN (3*EMB)          // 2304
#define FFN (4*EMB)           // 3072

// per-layer weight element counts ([N][K] layout) and type-major offsets
#define W_QKV (QKVN*EMB)
#define W_PROJ (EMB*EMB)
#define W_FC (FFN*EMB)
#define W_MLP (EMB*FFN)
#define OFF_QKV 0
#define OFF_PROJ (12*W_QKV)
#define OFF_FC (OFF_PROJ + 12*W_PROJ)
#define OFF_MLP (OFF_FC + 12*W_FC)
#define W_TOTAL (OFF_MLP + 12*W_MLP)

// ---------------- scratch (device globals; no allocation allowed) ----------
__device__ float g_h[BT*EMB];
__device__ float g_ln[BT*EMB];
__device__ float g_qkv[BT*QKVN];
__device__ float g_scores[(size_t)BATCH*NH*SEQ*SEQ];
__device__ float g_semb[VOC*EMB];
__device__ int   g_pre[BT];

__device__ __nv_bfloat16 g_wh[W_TOTAL];
__device__ __nv_bfloat16 g_wl[W_TOTAL];
__device__ __nv_bfloat16 g_lnh[BT*EMB], g_lnl[BT*EMB];
__device__ __nv_bfloat16 g_atth[BT*EMB], g_attl[BT*EMB];
__device__ __nv_bfloat16 g_midh[BT*FFN], g_midl[BT*FFN];

// ---------------- helpers ----------------
__device__ __forceinline__ uint32_t smem_u32(const void* p) {
    uint32_t a;
    asm("{ .reg .u64 t; cvta.to.shared.u64 t, %1; cvt.u32.u64 %0, t; }" : "=r"(a) : "l"(p));
    return a;
}

__device__ __forceinline__ void ldsm_x4(uint32_t* r, uint32_t addr) {
    asm volatile("ldmatrix.sync.aligned.m8n8.x4.shared.b16 {%0,%1,%2,%3}, [%4];"
        : "=r"(r[0]), "=r"(r[1]), "=r"(r[2]), "=r"(r[3]) : "r"(addr));
}

__device__ __forceinline__ void mma16816(float* c, const uint32_t* a, const uint32_t* b) {
    asm volatile("mma.sync.aligned.m16n8k16.row.col.f32.bf16.bf16.f32 "
        "{%0,%1,%2,%3}, {%4,%5,%6,%7}, {%8,%9}, {%0,%1,%2,%3};"
        : "+f"(c[0]), "+f"(c[1]), "+f"(c[2]), "+f"(c[3])
        : "r"(a[0]), "r"(a[1]), "r"(a[2]), "r"(a[3]), "r"(b[0]), "r"(b[1]));
}

__device__ __forceinline__ void cp16(uint32_t dst, const void* src) {
    asm volatile("cp.async.cg.shared.global [%0], [%1], 16;" :: "r"(dst), "l"(src));
}
#define CP_COMMIT() asm volatile("cp.async.commit_group;" ::: "memory")
#define CP_WAIT(n)  asm volatile("cp.async.wait_group %0;" :: "n"(n) : "memory")

__device__ __forceinline__ void cvt_split2(float x0, float x1, uint32_t& hi, uint32_t& lo) {
    __nv_bfloat16 h0 = __float2bfloat16_rn(x0);
    __nv_bfloat16 h1 = __float2bfloat16_rn(x1);
    __nv_bfloat16 l0 = __float2bfloat16_rn(x0 - __bfloat162float(h0));
    __nv_bfloat16 l1 = __float2bfloat16_rn(x1 - __bfloat162float(h1));
    __nv_bfloat162 H(h0, h1), L(l0, l1);
    hi = *(uint32_t*)&H;
    lo = *(uint32_t*)&L;
}

// ---------------- reductions ----------------
__device__ __forceinline__ float breduce_sum(float v, float* sh, int nthr) {
#pragma unroll
    for (int o = 16; o > 0; o >>= 1) v += __shfl_xor_sync(0xffffffffu, v, o);
    int lane = threadIdx.x & 31, w = threadIdx.x >> 5;
    if (lane == 0) sh[w] = v;
    __syncthreads();
    float r = 0.f;
    if ((int)threadIdx.x < (nthr >> 5)) r = sh[threadIdx.x];
    if (threadIdx.x < 32) {
#pragma unroll
        for (int o = 16; o > 0; o >>= 1) r += __shfl_xor_sync(0xffffffffu, r, o);
        if (threadIdx.x == 0) sh[0] = r;
    }
    __syncthreads();
    r = sh[0];
    __syncthreads();
    return r;
}

__device__ __forceinline__ float breduce_max(float v, float* sh, int nthr) {
#pragma unroll
    for (int o = 16; o > 0; o >>= 1) v = fmaxf(v, __shfl_xor_sync(0xffffffffu, v, o));
    int lane = threadIdx.x & 31, w = threadIdx.x >> 5;
    if (lane == 0) sh[w] = v;
    __syncthreads();
    float r = -3.0e38f;
    if ((int)threadIdx.x < (nthr >> 5)) r = sh[threadIdx.x];
    if (threadIdx.x < 32) {
#pragma unroll
        for (int o = 16; o > 0; o >>= 1) r = fmaxf(r, __shfl_xor_sync(0xffffffffu, r, o));
        if (threadIdx.x == 0) sh[0] = r;
    }
    __syncthreads();
    r = sh[0];
    __syncthreads();
    return r;
}

// ---------------- automaton state scan (LDS-resident) ----------------
__global__ void state_scan_kernel(const int* __restrict__ ids, const int* __restrict__ mul) {
    __shared__ int smul[VOC*VOC];
    __shared__ int sids[BT];
    int tid = threadIdx.x;
    for (int i = tid; i < VOC*VOC; i += blockDim.x) smul[i] = mul[i];
    for (int i = tid; i < BT; i += blockDim.x) sids[i] = ids[i];
    __syncthreads();
    if (tid < BATCH) {
        int s = 0;
        const int* row = sids + tid * SEQ;
        int* pre = g_pre + tid * SEQ;
        for (int t = 0; t < SEQ; t++) {
            pre[t] = s;
            s = smul[row[t] * VOC + s];
        }
    }
}

__global__ void state_proj_kernel(const float* __restrict__ semb,
                                  const float* __restrict__ W,
                                  const float* __restrict__ b) {
    int idx = blockIdx.x * blockDim.x + threadIdx.x;
    if (idx >= VOC * EMB) return;
    int v = idx / EMB, e = idx % EMB;
    float acc = b[e];
#pragma unroll 8
    for (int d = 0; d < DST; d++) acc += semb[v * DST + d] * W[d * EMB + e];
    g_semb[idx] = acc;
}

__global__ void embed_kernel(const int* __restrict__ ids,
                             const float* __restrict__ tok_emb,
                             const float* __restrict__ wpe) {
    int idx = blockIdx.x * blockDim.x + threadIdx.x;
    if (idx >= BT * EMB) return;
    int bt = idx / EMB, e = idx % EMB;
    int t = bt % SEQ;
    g_h[idx] = tok_emb[ids[bt] * EMB + e] + g_semb[g_pre[bt] * EMB + e] + wpe[t * EMB + e];
}

// ---------------- weight convert: W[K][N] fp32 -> Hi/Lo [N][K] bf16 --------
__global__ __launch_bounds__(256) void wconv_kernel(
    const float* __restrict__ W, __nv_bfloat16* __restrict__ Hi,
    __nv_bfloat16* __restrict__ Lo, int K, int N)
{
    __shared__ float t[32][33];
    int l = blockIdx.z;
    const float* Wl = W + (size_t)l * K * N;
    __nv_bfloat16* Hl = Hi + (size_t)l * K * N;
    __nv_bfloat16* Ll = Lo + (size_t)l * K * N;
    int n0 = blockIdx.x * 32, k0 = blockIdx.y * 32;
    int tx = threadIdx.x & 31, ty = threadIdx.x >> 5;
#pragma unroll
    for (int j = 0; j < 4; j++)
        t[ty + 8 * j][tx] = Wl[(size_t)(k0 + ty + 8 * j) * N + n0 + tx];
    __syncthreads();
#pragma unroll
    for (int j = 0; j < 4; j++) {
        float v = t[tx][ty + 8 * j];
        __nv_bfloat16 h = __float2bfloat16_rn(v);
        __nv_bfloat16 lo = __float2bfloat16_rn(v - __bfloat162float(h));
        size_t o = (size_t)(n0 + ty + 8 * j) * K + k0 + tx;
        Hl[o] = h;
        Ll[o] = lo;
    }
}

// ---------------- layernorm variants ----------------
__global__ __launch_bounds__(256) void ln_kernel(const float* __restrict__ x,
                                                 const float* __restrict__ g,
                                                 const float* __restrict__ b,
                                                 float* __restrict__ y) {
    __shared__ float sh[8];
    int row = blockIdx.x, tid = threadIdx.x;
    const float* xr = x + (size_t)row * EMB;
    float v0 = xr[tid], v1 = xr[tid + 256], v2 = xr[tid + 512];
    float mean = breduce_sum(v0 + v1 + v2, sh, 256) * (1.f / EMB);
    float d0 = v0 - mean, d1 = v1 - mean, d2 = v2 - mean;
    float var = breduce_sum(d0*d0 + d1*d1 + d2*d2, sh, 256) * (1.f / EMB);
    float rstd = rsqrtf(var + 1e-5f);
    float* yr = y + (size_t)row * EMB;
    yr[tid]       = d0 * rstd * g[tid]       + b[tid];
    yr[tid + 256] = d1 * rstd * g[tid + 256] + b[tid + 256];
    yr[tid + 512] = d2 * rstd * g[tid + 512] + b[tid + 512];
}

__global__ __launch_bounds__(256) void ln_bf16_kernel(const float* __restrict__ x,
                                                      const float* __restrict__ g,
                                                      const float* __restrict__ b,
                                                      __nv_bfloat16* __restrict__ yh,
                                                      __nv_bfloat16* __restrict__ yl) {
    __shared__ float sh[8];
    int row = blockIdx.x, tid = threadIdx.x;
    const float* xr = x + (size_t)row * EMB;
    float v0 = xr[tid], v1 = xr[tid + 256], v2 = xr[tid + 512];
    float mean = breduce_sum(v0 + v1 + v2, sh, 256) * (1.f / EMB);
    float d0 = v0 - mean, d1 = v1 - mean, d2 = v2 - mean;
    float var = breduce_sum(d0*d0 + d1*d1 + d2*d2, sh, 256) * (1.f / EMB);
    float rstd = rsqrtf(var + 1e-5f);
    size_t base = (size_t)row * EMB;
#pragma unroll
    for (int q = 0; q < 3; q++) {
        int e = tid + q * 256;
        float d = (q == 0) ? d0 : (q == 1) ? d1 : d2;
        float v = d * rstd * g[e] + b[e];
        __nv_bfloat16 h = __float2bfloat16_rn(v);
        yh[base + e] = h;
        yl[base + e] = __float2bfloat16_rn(v - __bfloat162float(h));
    }
}

// ================= mma.sync bf16-split GEMM (2 CTAs/SM) ====================
// CTA tile 128(M) x 64(N); 8 warps 4(M)x2(N); warp tile 32x32; K-chunk 32.
// Double-buffered cp.async; 3 split MMAs per fragment pair.

__device__ __forceinline__ float gelu_f(float x) {
    return 0.5f * x * (1.f + tanhf(0.7978845608028654f * (x + 0.044715f * x * x * x)));
}

#define ROWB 80
#define SM_AH 0
#define SM_AL 10240
#define SM_BH 20480
#define SM_BL 25600
#define BUFSZ 30720
#define GEMM_SMEM (2*BUFSZ)   // 61440

// EPI: 0 = fp32 C=acc+bias; 1 = fp32 C=acc+bias+Res; 2 = bf16 split of gelu(acc+bias)
template<int EPI>
__global__ __launch_bounds__(256, 2) void mma_gemm(
    const __nv_bfloat16* __restrict__ Ah, const __nv_bfloat16* __restrict__ Al,
    const __nv_bfloat16* __restrict__ Bh, const __nv_bfloat16* __restrict__ Bl,
    const float* __restrict__ bias,
    const float* __restrict__ Res,
    float* __restrict__ C,
    __nv_bfloat16* __restrict__ Ch, __nv_bfloat16* __restrict__ Cl,
    int K, int N)
{
    extern __shared__ __align__(16) char sm[];
    uint32_t sb = smem_u32(sm);
    int tid = threadIdx.x;
    int wid = tid >> 5, lane = tid & 31;
    int wm = wid & 3, wn = wid >> 2;
    int m0 = blockIdx.y * 128, n0 = blockIdx.x * 64;

    int p_row = tid >> 2;     // 0..63
    int p_seg = tid & 3;

    int a_row = lane & 15;
    int a_colb = ((lane >> 4) * 8) * 2;
    int b_row = (lane & 7) + ((lane >> 4) & 1) * 8;
    int b_colb = (((lane >> 3) & 1) * 8) * 2;

    float acc[2][4][4];
#pragma unroll
    for (int i = 0; i < 2; i++)
#pragma unroll
        for (int j = 0; j < 4; j++)
#pragma unroll
            for (int q = 0; q < 4; q++) acc[i][j][q] = 0.f;

    const int nch = K >> 5;

    auto issue = [&](int c, int bufsel) {
        int k0 = c << 5;
        uint32_t base = sb + bufsel * BUFSZ;
        uint32_t doff = (uint32_t)(p_row * ROWB + p_seg * 16);
#pragma unroll
        for (int i = 0; i < 2; i++) {
            int row = p_row + i * 64;
            size_t aoff = (size_t)(m0 + row) * K + k0 + p_seg * 8;
            cp16(base + SM_AH + doff + i * (64 * ROWB), Ah + aoff);
            cp16(base + SM_AL + doff + i * (64 * ROWB), Al + aoff);
        }
        size_t boff = (size_t)(n0 + p_row) * K + k0 + p_seg * 8;
        cp16(base + SM_BH + doff, Bh + boff);
        cp16(base + SM_BL + doff, Bl + boff);
    };

    issue(0, 0);
    CP_COMMIT();

    for (int c = 0; c < nch; c++) {
        int cur = c & 1;
        if (c + 1 < nch) {
            issue(c + 1, cur ^ 1);
            CP_COMMIT();
            CP_WAIT(1);
        } else {
            CP_WAIT(0);
        }
        __syncthreads();

        uint32_t base = sb + cur * BUFSZ;
#pragma unroll
        for (int ks = 0; ks < 2; ks++) {
            uint32_t a_hi[2][4], a_lo[2][4];
#pragma unroll
            for (int mt = 0; mt < 2; mt++) {
                uint32_t off = (uint32_t)((wm * 32 + mt * 16 + a_row) * ROWB
                                          + ks * 32 + a_colb);
                ldsm_x4(a_hi[mt], base + SM_AH + off);
                ldsm_x4(a_lo[mt], base + SM_AL + off);
            }
            uint32_t b_hi[2][4], b_lo[2][4];
#pragma unroll
            for (int p = 0; p < 2; p++) {
                uint32_t off = (uint32_t)((wn * 32 + p * 16 + b_row) * ROWB
                                          + ks * 32 + b_colb);
                ldsm_x4(b_hi[p], base + SM_BH + off);
                ldsm_x4(b_lo[p], base + SM_BL + off);
            }
#pragma unroll
            for (int mt = 0; mt < 2; mt++)
#pragma unroll
                for (int p = 0; p < 2; p++) {
                    mma16816(acc[mt][2*p],   a_hi[mt], &b_hi[p][0]);
                    mma16816(acc[mt][2*p+1], a_hi[mt], &b_hi[p][2]);
                }
#pragma unroll
            for (int mt = 0; mt < 2; mt++)
#pragma unroll
                for (int p = 0; p < 2; p++) {
                    mma16816(acc[mt][2*p],   a_hi[mt], &b_lo[p][0]);
                    mma16816(acc[mt][2*p+1], a_hi[mt], &b_lo[p][2]);
                }
#pragma unroll
            for (int mt = 0; mt < 2; mt++)
#pragma unroll
                for (int p = 0; p < 2; p++) {
                    mma16816(acc[mt][2*p],   a_lo[mt], &b_hi[p][0]);
                    mma16816(acc[mt][2*p+1], a_lo[mt], &b_hi[p][2]);
                }
        }
        __syncthreads();
    }

    // ---- epilogue ----
    int r0 = m0 + wm * 32 + (lane >> 2);
    int c0 = n0 + wn * 32 + (lane & 3) * 2;
#pragma unroll
    for (int mt = 0; mt < 2; mt++) {
#pragma unroll
        for (int nt = 0; nt < 4; nt++) {
            int r = r0 + mt * 16;
            int cc = c0 + nt * 8;
            float b0 = bias[cc], b1 = bias[cc + 1];
            float v0 = acc[mt][nt][0] + b0;
            float v1 = acc[mt][nt][1] + b1;
            float v2 = acc[mt][nt][2] + b0;
            float v3 = acc[mt][nt][3] + b1;
            if (EPI == 2) {
                v0 = gelu_f(v0); v1 = gelu_f(v1);
                v2 = gelu_f(v2); v3 = gelu_f(v3);
                uint32_t h01, l01, h23, l23;
                cvt_split2(v0, v1, h01, l01);
                cvt_split2(v2, v3, h23, l23);
                *(uint32_t*)(Ch + (size_t)r * N + cc) = h01;
                *(uint32_t*)(Cl + (size_t)r * N + cc) = l01;
                *(uint32_t*)(Ch + (size_t)(r + 8) * N + cc) = h23;
                *(uint32_t*)(Cl + (size_t)(r + 8) * N + cc) = l23;
            } else {
                if (EPI == 1) {
                    const float* rp0 = Res + (size_t)r * N + cc;
                    const float* rp1 = Res + (size_t)(r + 8) * N + cc;
                    v0 += rp0[0]; v1 += rp0[1];
                    v2 += rp1[0]; v3 += rp1[1];
                }
                *reinterpret_cast<float2*>(C + (size_t)r * N + cc) = make_float2(v0, v1);
                *reinterpret_cast<float2*>(C + (size_t)(r + 8) * N + cc) = make_float2(v2, v3);
            }
        }
    }
}

// ---------------- small FFMA GEMM kept for the head (N=60) -----------------
__global__ __launch_bounds__(256) void head_gemm_kernel(
    const float* __restrict__ A,
    const float* __restrict__ Bm,
    const float* __restrict__ bias,
    float* __restrict__ C,
    int N, int K)
{
    __shared__ float As[16][68];
    __shared__ float Bs[16][64];
    int m0 = blockIdx.y * 64, n0 = blockIdx.x * 64;
    int tid = threadIdx.x;
    int tx = tid & 15, ty = tid >> 4;
    float acc[4][4] = {};
    for (int k0 = 0; k0 < K; k0 += 16) {
#pragma unroll
        for (int i = 0; i < 4; i++) {
            int lin = tid + i * 256;
            int r = lin >> 4, c = lin & 15;
            As[c][r] = A[(size_t)(m0 + r) * K + k0 + c];
        }
#pragma unroll
        for (int i = 0; i < 4; i++) {
            int lin = tid + i * 256;
            int r = lin >> 6, c = lin & 63;
            int n = n0 + c;
            Bs[r][c] = (n < N) ? Bm[(size_t)(k0 + r) * N + n] : 0.f;
        }
        __syncthreads();
#pragma unroll
        for (int kk = 0; kk < 16; kk++) {
            float4 a4 = *reinterpret_cast<const float4*>(&As[kk][ty * 4]);
            float4 b4 = *reinterpret_cast<const float4*>(&Bs[kk][tx * 4]);
            float a[4] = {a4.x, a4.y, a4.z, a4.w};
            float bv[4] = {b4.x, b4.y, b4.z, b4.w};
#pragma unroll
            for (int i = 0; i < 4; i++)
#pragma unroll
                for (int j = 0; j < 4; j++)
                    acc[i][j] = fmaf(a[i], bv[j], acc[i][j]);
        }
        __syncthreads();
    }
#pragma unroll
    for (int i = 0; i < 4; i++) {
        int m = m0 + ty * 4 + i;
#pragma unroll
        for (int j = 0; j < 4; j++) {
            int n = n0 + tx * 4 + j;
            if (n < N) C[(size_t)m * N + n] = acc[i][j] + bias[n];
        }
    }
}

// ---------------- attention ----------------
__global__ __launch_bounds__(256) void attn_scores_kernel() {
    int bh = blockIdx.z;
    int b = bh / NH, h = bh % NH;
    int t0 = blockIdx.y * 64, s0 = blockIdx.x * 64;
    if (s0 > t0 + 63) return;
    const float* qb = g_qkv + (size_t)b * SEQ * QKVN + h * DH;
    const float* kb = g_qkv + (size_t)b * SEQ * QKVN + EMB + h * DH;
    float* Sb = g_scores + (size_t)bh * SEQ * SEQ;
    __shared__ float Qs[64][65];
    __shared__ float Ks[64][65];
    int tid = threadIdx.x;
    int tx = tid & 15, ty = tid >> 4;
#pragma unroll
    for (int i = 0; i < 16; i++) {
        int lin = tid + i * 256;
        int r = lin >> 6, c = lin & 63;
        Qs[c][r] = qb[(size_t)(t0 + r) * QKVN + c];
        Ks[c][r] = kb[(size_t)(s0 + r) * QKVN + c];
    }
    __syncthreads();
    float acc[4][4] = {};
#pragma unroll 8
    for (int kk = 0; kk < 64; kk++) {
        float a[4], bv[4];
#pragma unroll
        for (int i = 0; i < 4; i++) a[i] = Qs[kk][ty * 4 + i];
#pragma unroll
        for (int j = 0; j < 4; j++) bv[j] = Ks[kk][tx * 4 + j];
#pragma unroll
        for (int i = 0; i < 4; i++)
#pragma unroll
            for (int j = 0; j < 4; j++)
                acc[i][j] = fmaf(a[i], bv[j], acc[i][j]);
    }
    const float scale = 0.125f;
#pragma unroll
    for (int i = 0; i < 4; i++) {
        int t = t0 + ty * 4 + i;
#pragma unroll
        for (int j = 0; j < 4; j++) {
            int s = s0 + tx * 4 + j;
            Sb[(size_t)t * SEQ + s] = acc[i][j] * scale;
        }
    }
}

__global__ __launch_bounds__(128) void softmax_kernel() {
    __shared__ float sh[4];
    int r = blockIdx.x;
    int t = r & (SEQ - 1);
    float* row = g_scores + (size_t)r * SEQ;
    int n = t + 1;
    int tid = threadIdx.x;
    float mx = -3.0e38f;
    for (int i = tid; i < n; i += 128) mx = fmaxf(mx, row[i]);
    mx = breduce_max(mx, sh, 128);
    float sum = 0.f;
    for (int i = tid; i < n; i += 128) {
        float e = __expf(row[i] - mx);
        row[i] = e;
        sum += e;
    }
    sum = breduce_sum(sum, sh, 128);
    float inv = 1.f / sum;
    for (int i = tid; i < n; i += 128) row[i] *= inv;
    int zend = ((t >> 6) + 1) << 6;
    for (int i = n + tid; i < zend; i += 128) row[i] = 0.f;
}

__global__ __launch_bounds__(256) void attn_pv_kernel() {
    int bh = blockIdx.z;
    int b = bh / NH, h = bh % NH;
    int t0 = blockIdx.y * 64;
    const float* Pb = g_scores + (size_t)bh * SEQ * SEQ;
    const float* vb = g_qkv + (size_t)b * SEQ * QKVN + 2 * EMB + h * DH;
    __shared__ float Ps[16][68];
    __shared__ float Vs[16][64];
    int tid = threadIdx.x;
    int tx = tid & 15, ty = tid >> 4;
    float acc[4][4] = {};
    int kend = t0 + 64;
    for (int k0 = 0; k0 < kend; k0 += 16) {
#pragma unroll
        for (int i = 0; i < 4; i++) {
            int lin = tid + i * 256;
            int r = lin >> 4, c = lin & 15;
            Ps[c][r] = Pb[(size_t)(t0 + r) * SEQ + k0 + c];
        }
#pragma unroll
        for (int i = 0; i < 4; i++) {
            int lin = tid + i * 256;
            int r = lin >> 6, c = lin & 63;
            Vs[r][c] = vb[(size_t)(k0 + r) * QKVN + c];
        }
        __syncthreads();
#pragma unroll
        for (int kk = 0; kk < 16; kk++) {
            float4 a4 = *reinterpret_cast<const float4*>(&Ps[kk][ty * 4]);
            float4 b4 = *reinterpret_cast<const float4*>(&Vs[kk][tx * 4]);
            float a[4] = {a4.x, a4.y, a4.z, a4.w};
            float bv[4] = {b4.x, b4.y, b4.z, b4.w};
#pragma unroll
            for (int i = 0; i < 4; i++)
#pragma unroll
                for (int j = 0; j < 4; j++)
                    acc[i][j] = fmaf(a[i], bv[j], acc[i][j]);
        }
        __syncthreads();
    }
#pragma unroll
    for (int i = 0; i < 4; i++) {
        int t = t0 + ty * 4 + i;
        size_t base = (size_t)(b * SEQ + t) * EMB + h * DH + tx * 4;
        uint32_t h01, l01, h23, l23;
        cvt_split2(acc[i][0], acc[i][1], h01, l01);
        cvt_split2(acc[i][2], acc[i][3], h23, l23);
        *(uint32_t*)(g_atth + base)     = h01;
        *(uint32_t*)(g_attl + base)     = l01;
        *(uint32_t*)(g_atth + base + 2) = h23;
        *(uint32_t*)(g_attl + base + 2) = l23;
    }
}

// ---------------- host orchestration ----------------
extern "C" void kernel_launch(void* const* d_in, const int* in_sizes, int n_in,
                              void* d_out, int out_size) {
    const int*   ids          = (const int*)d_in[0];
    const int*   mul          = (const int*)d_in[1];
    const float* tok_emb      = (const float*)d_in[2];
    const float* state_emb    = (const float*)d_in[3];
    const float* state_proj_w = (const float*)d_in[4];
    const float* state_proj_b = (const float*)d_in[5];
    const float* wpe          = (const float*)d_in[6];
    const float* ln1_g        = (const float*)d_in[7];
    const float* ln1_b        = (const float*)d_in[8];
    const float* attn_w       = (const float*)d_in[9];
    const float* attn_b       = (const float*)d_in[10];
    const float* attn_proj_w  = (const float*)d_in[11];
    const float* attn_proj_b  = (const float*)d_in[12];
    const float* ln2_g        = (const float*)d_in[13];
    const float* ln2_b        = (const float*)d_in[14];
    const float* fc_w         = (const float*)d_in[15];
    const float* fc_b         = (const float*)d_in[16];
    const float* mlp_proj_w   = (const float*)d_in[17];
    const float* mlp_proj_b   = (const float*)d_in[18];
    const float* lnf_g        = (const float*)d_in[19];
    const float* lnf_b        = (const float*)d_in[20];
    const float* head_w       = (const float*)d_in[21];
    const float* head_b       = (const float*)d_in[22];
    float* out = (float*)d_out;

    float *h, *lnbuf, *qkv;
    __nv_bfloat16 *wh, *wl, *lnh, *lnl, *atth, *attl, *midh, *midl;
    cudaGetSymbolAddress((void**)&h,     g_h);
    cudaGetSymbolAddress((void**)&lnbuf, g_ln);
    cudaGetSymbolAddress((void**)&qkv,   g_qkv);
    cudaGetSymbolAddress((void**)&wh,    g_wh);
    cudaGetSymbolAddress((void**)&wl,    g_wl);
    cudaGetSymbolAddress((void**)&lnh,   g_lnh);
    cudaGetSymbolAddress((void**)&lnl,   g_lnl);
    cudaGetSymbolAddress((void**)&atth,  g_atth);
    cudaGetSymbolAddress((void**)&attl,  g_attl);
    cudaGetSymbolAddress((void**)&midh,  g_midh);
    cudaGetSymbolAddress((void**)&midl,  g_midl);

    cudaFuncSetAttribute(mma_gemm<0>, cudaFuncAttributeMaxDynamicSharedMemorySize, GEMM_SMEM);
    cudaFuncSetAttribute(mma_gemm<1>, cudaFuncAttributeMaxDynamicSharedMemorySize, GEMM_SMEM);
    cudaFuncSetAttribute(mma_gemm<2>, cudaFuncAttributeMaxDynamicSharedMemorySize, GEMM_SMEM);

    wconv_kernel<<<dim3(QKVN/32, EMB/32, NLAYER), 256>>>(attn_w, wh + OFF_QKV, wl + OFF_QKV, EMB, QKVN);
    wconv_kernel<<<dim3(EMB/32, EMB/32, NLAYER), 256>>>(attn_proj_w, wh + OFF_PROJ, wl + OFF_PROJ, EMB, EMB);
    wconv_kernel<<<dim3(FFN/32, EMB/32, NLAYER), 256>>>(fc_w, wh + OFF_FC, wl + OFF_FC, EMB, FFN);
    wconv_kernel<<<dim3(EMB/32, FFN/32, NLAYER), 256>>>(mlp_proj_w, wh + OFF_MLP, wl + OFF_MLP, FFN, EMB);

    state_scan_kernel<<<1, 256>>>(ids, mul);
    state_proj_kernel<<<(VOC * EMB + 255) / 256, 256>>>(state_emb, state_proj_w, state_proj_b);
    embed_kernel<<<(BT * EMB + 255) / 256, 256>>>(ids, tok_emb, wpe);

    for (int l = 0; l < NLAYER; l++) {
        ln_bf16_kernel<<<BT, 256>>>(h, ln1_g + l * EMB, ln1_b + l * EMB, lnh, lnl);
        mma_gemm<0><<<dim3(QKVN/64, BT/128), 256, GEMM_SMEM>>>(
            lnh, lnl, wh + OFF_QKV + (size_t)l * W_QKV, wl + OFF_QKV + (size_t)l * W_QKV,
            attn_b + l * QKVN, nullptr, qkv, nullptr, nullptr, EMB, QKVN);
        attn_scores_kernel<<<dim3(8, 8, BATCH * NH), 256>>>();
        softmax_kernel<<<BATCH * NH * SEQ, 128>>>();
        attn_pv_kernel<<<dim3(1, 8, BATCH * NH), 256>>>();
        mma_gemm<1><<<dim3(EMB/64, BT/128), 256, GEMM_SMEM>>>(
            atth, attl, wh + OFF_PROJ + (size_t)l * W_PROJ, wl + OFF_PROJ + (size_t)l * W_PROJ,
            attn_proj_b + l * EMB, h, h, nullptr, nullptr, EMB, EMB);
        ln_bf16_kernel<<<BT, 256>>>(h, ln2_g + l * EMB, ln2_b + l * EMB, lnh, lnl);
        mma_gemm<2><<<dim3(FFN/64, BT/128), 256, GEMM_SMEM>>>(
            lnh, lnl, wh + OFF_FC + (size_t)l * W_FC, wl + OFF_FC + (size_t)l * W_FC,
            fc_b + l * FFN, nullptr, nullptr, midh, midl, EMB, FFN);
        mma_gemm<1><<<dim3(EMB/64, BT/128), 256, GEMM_SMEM>>>(
            midh, midl, wh + OFF_MLP + (size_t)l * W_MLP, wl + OFF_MLP + (size_t)l * W_MLP,
            mlp_proj_b + l * EMB, h, h, nullptr, nullptr, FFN, EMB);
    }

    ln_kernel<<<BT, 256>>>(h, lnf_g, lnf_b, lnbuf);
    head_gemm_kernel<<<dim3(1, BT / 64), 256>>>(lnbuf, head_w, head_b, out, VOC, EMB);
}

// round 6
// speedup vs baseline: 2.4339x; 1.0323x over previous
#include <cuda_runtime.h>
#include <cuda_bf16.h>
#include <math.h>
#include <stdint.h>

#define BATCH 8
#define SEQ 512
#define BT (BATCH*SEQ)        // 4096
#define EMB 768
#define NH 12
#define DH 64
#define VOC 60
#define DST 128
#define NLAYER 12
#define QKVN (3*EMB)          // 2304
#define FFN (4*EMB)           // 3072

#define W_QKV (QKVN*EMB)
#define W_PROJ (EMB*EMB)
#define W_FC (FFN*EMB)
#define W_MLP (EMB*FFN)
#define OFF_QKV 0
#define OFF_PROJ (12*W_QKV)
#define OFF_FC (OFF_PROJ + 12*W_PROJ)
#define OFF_MLP (OFF_FC + 12*W_FC)
#define W_TOTAL (OFF_MLP + 12*W_MLP)

// ---------------- scratch ----------------
__device__ float g_h[BT*EMB];
__device__ float g_ln[BT*EMB];
__device__ float g_qkv[BT*QKVN];
__device__ float g_semb[VOC*EMB];
__device__ int   g_pre[BT];

__device__ __nv_bfloat16 g_wh[W_TOTAL];
__device__ __nv_bfloat16 g_wl[W_TOTAL];
__device__ __nv_bfloat16 g_lnh[BT*EMB], g_lnl[BT*EMB];
__device__ __nv_bfloat16 g_atth[BT*EMB], g_attl[BT*EMB];
__device__ __nv_bfloat16 g_midh[BT*FFN], g_midl[BT*FFN];

// ---------------- helpers ----------------
__device__ __forceinline__ uint32_t smem_u32(const void* p) {
    uint32_t a;
    asm("{ .reg .u64 t; cvta.to.shared.u64 t, %1; cvt.u32.u64 %0, t; }" : "=r"(a) : "l"(p));
    return a;
}

__device__ __forceinline__ void ldsm_x4(uint32_t* r, uint32_t addr) {
    asm volatile("ldmatrix.sync.aligned.m8n8.x4.shared.b16 {%0,%1,%2,%3}, [%4];"
        : "=r"(r[0]), "=r"(r[1]), "=r"(r[2]), "=r"(r[3]) : "r"(addr));
}

__device__ __forceinline__ void mma16816(float* c, const uint32_t* a, const uint32_t* b) {
    asm volatile("mma.sync.aligned.m16n8k16.row.col.f32.bf16.bf16.f32 "
        "{%0,%1,%2,%3}, {%4,%5,%6,%7}, {%8,%9}, {%0,%1,%2,%3};"
        : "+f"(c[0]), "+f"(c[1]), "+f"(c[2]), "+f"(c[3])
        : "r"(a[0]), "r"(a[1]), "r"(a[2]), "r"(a[3]), "r"(b[0]), "r"(b[1]));
}

__device__ __forceinline__ void cp16(uint32_t dst, const void* src) {
    asm volatile("cp.async.cg.shared.global [%0], [%1], 16;" :: "r"(dst), "l"(src));
}
#define CP_COMMIT() asm volatile("cp.async.commit_group;" ::: "memory")
#define CP_WAIT(n)  asm volatile("cp.async.wait_group %0;" :: "n"(n) : "memory")

__device__ __forceinline__ void cvt_split2(float x0, float x1, uint32_t& hi, uint32_t& lo) {
    __nv_bfloat16 h0 = __float2bfloat16_rn(x0);
    __nv_bfloat16 h1 = __float2bfloat16_rn(x1);
    __nv_bfloat16 l0 = __float2bfloat16_rn(x0 - __bfloat162float(h0));
    __nv_bfloat16 l1 = __float2bfloat16_rn(x1 - __bfloat162float(h1));
    __nv_bfloat162 H(h0, h1), L(l0, l1);
    hi = *(uint32_t*)&H;
    lo = *(uint32_t*)&L;
}

// ---------------- reductions ----------------
__device__ __forceinline__ float breduce_sum(float v, float* sh, int nthr) {
#pragma unroll
    for (int o = 16; o > 0; o >>= 1) v += __shfl_xor_sync(0xffffffffu, v, o);
    int lane = threadIdx.x & 31, w = threadIdx.x >> 5;
    if (lane == 0) sh[w] = v;
    __syncthreads();
    float r = 0.f;
    if ((int)threadIdx.x < (nthr >> 5)) r = sh[threadIdx.x];
    if (threadIdx.x < 32) {
#pragma unroll
        for (int o = 16; o > 0; o >>= 1) r += __shfl_xor_sync(0xffffffffu, r, o);
        if (threadIdx.x == 0) sh[0] = r;
    }
    __syncthreads();
    r = sh[0];
    __syncthreads();
    return r;
}

// ---------------- automaton state scan ----------------
__global__ void state_scan_kernel(const int* __restrict__ ids, const int* __restrict__ mul) {
    __shared__ int smul[VOC*VOC];
    __shared__ int sids[BT];
    int tid = threadIdx.x;
    for (int i = tid; i < VOC*VOC; i += blockDim.x) smul[i] = mul[i];
    for (int i = tid; i < BT; i += blockDim.x) sids[i] = ids[i];
    __syncthreads();
    if (tid < BATCH) {
        int s = 0;
        const int* row = sids + tid * SEQ;
        int* pre = g_pre + tid * SEQ;
        for (int t = 0; t < SEQ; t++) {
            pre[t] = s;
            s = smul[row[t] * VOC + s];
        }
    }
}

__global__ void state_proj_kernel(const float* __restrict__ semb,
                                  const float* __restrict__ W,
                                  const float* __restrict__ b) {
    int idx = blockIdx.x * blockDim.x + threadIdx.x;
    if (idx >= VOC * EMB) return;
    int v = idx / EMB, e = idx % EMB;
    float acc = b[e];
#pragma unroll 8
    for (int d = 0; d < DST; d++) acc += semb[v * DST + d] * W[d * EMB + e];
    g_semb[idx] = acc;
}

__global__ void embed_kernel(const int* __restrict__ ids,
                             const float* __restrict__ tok_emb,
                             const float* __restrict__ wpe) {
    int idx = blockIdx.x * blockDim.x + threadIdx.x;
    if (idx >= BT * EMB) return;
    int bt = idx / EMB, e = idx % EMB;
    int t = bt % SEQ;
    g_h[idx] = tok_emb[ids[bt] * EMB + e] + g_semb[g_pre[bt] * EMB + e] + wpe[t * EMB + e];
}

// ---------------- weight convert ----------------
__global__ __launch_bounds__(256) void wconv_kernel(
    const float* __restrict__ W, __nv_bfloat16* __restrict__ Hi,
    __nv_bfloat16* __restrict__ Lo, int K, int N)
{
    __shared__ float t[32][33];
    int l = blockIdx.z;
    const float* Wl = W + (size_t)l * K * N;
    __nv_bfloat16* Hl = Hi + (size_t)l * K * N;
    __nv_bfloat16* Ll = Lo + (size_t)l * K * N;
    int n0 = blockIdx.x * 32, k0 = blockIdx.y * 32;
    int tx = threadIdx.x & 31, ty = threadIdx.x >> 5;
#pragma unroll
    for (int j = 0; j < 4; j++)
        t[ty + 8 * j][tx] = Wl[(size_t)(k0 + ty + 8 * j) * N + n0 + tx];
    __syncthreads();
#pragma unroll
    for (int j = 0; j < 4; j++) {
        float v = t[tx][ty + 8 * j];
        __nv_bfloat16 h = __float2bfloat16_rn(v);
        __nv_bfloat16 lo = __float2bfloat16_rn(v - __bfloat162float(h));
        size_t o = (size_t)(n0 + ty + 8 * j) * K + k0 + tx;
        Hl[o] = h;
        Ll[o] = lo;
    }
}

// ---------------- layernorm variants ----------------
__global__ __launch_bounds__(256) void ln_kernel(const float* __restrict__ x,
                                                 const float* __restrict__ g,
                                                 const float* __restrict__ b,
                                                 float* __restrict__ y) {
    __shared__ float sh[8];
    int row = blockIdx.x, tid = threadIdx.x;
    const float* xr = x + (size_t)row * EMB;
    float v0 = xr[tid], v1 = xr[tid + 256], v2 = xr[tid + 512];
    float mean = breduce_sum(v0 + v1 + v2, sh, 256) * (1.f / EMB);
    float d0 = v0 - mean, d1 = v1 - mean, d2 = v2 - mean;
    float var = breduce_sum(d0*d0 + d1*d1 + d2*d2, sh, 256) * (1.f / EMB);
    float rstd = rsqrtf(var + 1e-5f);
    float* yr = y + (size_t)row * EMB;
    yr[tid]       = d0 * rstd * g[tid]       + b[tid];
    yr[tid + 256] = d1 * rstd * g[tid + 256] + b[tid + 256];
    yr[tid + 512] = d2 * rstd * g[tid + 512] + b[tid + 512];
}

__global__ __launch_bounds__(256) void ln_bf16_kernel(const float* __restrict__ x,
                                                      const float* __restrict__ g,
                                                      const float* __restrict__ b,
                                                      __nv_bfloat16* __restrict__ yh,
                                                      __nv_bfloat16* __restrict__ yl) {
    __shared__ float sh[8];
    int row = blockIdx.x, tid = threadIdx.x;
    const float* xr = x + (size_t)row * EMB;
    float v0 = xr[tid], v1 = xr[tid + 256], v2 = xr[tid + 512];
    float mean = breduce_sum(v0 + v1 + v2, sh, 256) * (1.f / EMB);
    float d0 = v0 - mean, d1 = v1 - mean, d2 = v2 - mean;
    float var = breduce_sum(d0*d0 + d1*d1 + d2*d2, sh, 256) * (1.f / EMB);
    float rstd = rsqrtf(var + 1e-5f);
    size_t base = (size_t)row * EMB;
#pragma unroll
    for (int q = 0; q < 3; q++) {
        int e = tid + q * 256;
        float d = (q == 0) ? d0 : (q == 1) ? d1 : d2;
        float v = d * rstd * g[e] + b[e];
        __nv_bfloat16 h = __float2bfloat16_rn(v);
        yh[base + e] = h;
        yl[base + e] = __float2bfloat16_rn(v - __bfloat162float(h));
    }
}

// ================= mma.sync bf16-split GEMM (2 CTAs/SM) ====================
__device__ __forceinline__ float gelu_f(float x) {
    return 0.5f * x * (1.f + tanhf(0.7978845608028654f * (x + 0.044715f * x * x * x)));
}

#define ROWB 80
#define SM_AH 0
#define SM_AL 10240
#define SM_BH 20480
#define SM_BL 25600
#define BUFSZ 30720
#define GEMM_SMEM (2*BUFSZ)

template<int EPI>
__global__ __launch_bounds__(256, 2) void mma_gemm(
    const __nv_bfloat16* __restrict__ Ah, const __nv_bfloat16* __restrict__ Al,
    const __nv_bfloat16* __restrict__ Bh, const __nv_bfloat16* __restrict__ Bl,
    const float* __restrict__ bias,
    const float* __restrict__ Res,
    float* __restrict__ C,
    __nv_bfloat16* __restrict__ Ch, __nv_bfloat16* __restrict__ Cl,
    int K, int N)
{
    extern __shared__ __align__(16) char sm[];
    uint32_t sb = smem_u32(sm);
    int tid = threadIdx.x;
    int wid = tid >> 5, lane = tid & 31;
    int wm = wid & 3, wn = wid >> 2;
    int m0 = blockIdx.y * 128, n0 = blockIdx.x * 64;

    int p_row = tid >> 2;
    int p_seg = tid & 3;

    int a_row = lane & 15;
    int a_colb = ((lane >> 4) * 8) * 2;
    int b_row = (lane & 7) + ((lane >> 4) & 1) * 8;
    int b_colb = (((lane >> 3) & 1) * 8) * 2;

    float acc[2][4][4];
#pragma unroll
    for (int i = 0; i < 2; i++)
#pragma unroll
        for (int j = 0; j < 4; j++)
#pragma unroll
            for (int q = 0; q < 4; q++) acc[i][j][q] = 0.f;

    const int nch = K >> 5;

    auto issue = [&](int c, int bufsel) {
        int k0 = c << 5;
        uint32_t base = sb + bufsel * BUFSZ;
        uint32_t doff = (uint32_t)(p_row * ROWB + p_seg * 16);
#pragma unroll
        for (int i = 0; i < 2; i++) {
            int row = p_row + i * 64;
            size_t aoff = (size_t)(m0 + row) * K + k0 + p_seg * 8;
            cp16(base + SM_AH + doff + i * (64 * ROWB), Ah + aoff);
            cp16(base + SM_AL + doff + i * (64 * ROWB), Al + aoff);
        }
        size_t boff = (size_t)(n0 + p_row) * K + k0 + p_seg * 8;
        cp16(base + SM_BH + doff, Bh + boff);
        cp16(base + SM_BL + doff, Bl + boff);
    };

    issue(0, 0);
    CP_COMMIT();

    for (int c = 0; c < nch; c++) {
        int cur = c & 1;
        if (c + 1 < nch) {
            issue(c + 1, cur ^ 1);
            CP_COMMIT();
            CP_WAIT(1);
        } else {
            CP_WAIT(0);
        }
        __syncthreads();

        uint32_t base = sb + cur * BUFSZ;
#pragma unroll
        for (int ks = 0; ks < 2; ks++) {
            uint32_t a_hi[2][4], a_lo[2][4];
#pragma unroll
            for (int mt = 0; mt < 2; mt++) {
                uint32_t off = (uint32_t)((wm * 32 + mt * 16 + a_row) * ROWB
                                          + ks * 32 + a_colb);
                ldsm_x4(a_hi[mt], base + SM_AH + off);
                ldsm_x4(a_lo[mt], base + SM_AL + off);
            }
            uint32_t b_hi[2][4], b_lo[2][4];
#pragma unroll
            for (int p = 0; p < 2; p++) {
                uint32_t off = (uint32_t)((wn * 32 + p * 16 + b_row) * ROWB
                                          + ks * 32 + b_colb);
                ldsm_x4(b_hi[p], base + SM_BH + off);
                ldsm_x4(b_lo[p], base + SM_BL + off);
            }
#pragma unroll
            for (int mt = 0; mt < 2; mt++)
#pragma unroll
                for (int p = 0; p < 2; p++) {
                    mma16816(acc[mt][2*p],   a_hi[mt], &b_hi[p][0]);
                    mma16816(acc[mt][2*p+1], a_hi[mt], &b_hi[p][2]);
                }
#pragma unroll
            for (int mt = 0; mt < 2; mt++)
#pragma unroll
                for (int p = 0; p < 2; p++) {
                    mma16816(acc[mt][2*p],   a_hi[mt], &b_lo[p][0]);
                    mma16816(acc[mt][2*p+1], a_hi[mt], &b_lo[p][2]);
                }
#pragma unroll
            for (int mt = 0; mt < 2; mt++)
#pragma unroll
                for (int p = 0; p < 2; p++) {
                    mma16816(acc[mt][2*p],   a_lo[mt], &b_hi[p][0]);
                    mma16816(acc[mt][2*p+1], a_lo[mt], &b_hi[p][2]);
                }
        }
        __syncthreads();
    }

    int r0 = m0 + wm * 32 + (lane >> 2);
    int c0 = n0 + wn * 32 + (lane & 3) * 2;
#pragma unroll
    for (int mt = 0; mt < 2; mt++) {
#pragma unroll
        for (int nt = 0; nt < 4; nt++) {
            int r = r0 + mt * 16;
            int cc = c0 + nt * 8;
            float b0 = bias[cc], b1 = bias[cc + 1];
            float v0 = acc[mt][nt][0] + b0;
            float v1 = acc[mt][nt][1] + b1;
            float v2 = acc[mt][nt][2] + b0;
            float v3 = acc[mt][nt][3] + b1;
            if (EPI == 2) {
                v0 = gelu_f(v0); v1 = gelu_f(v1);
                v2 = gelu_f(v2); v3 = gelu_f(v3);
                uint32_t h01, l01, h23, l23;
                cvt_split2(v0, v1, h01, l01);
                cvt_split2(v2, v3, h23, l23);
                *(uint32_t*)(Ch + (size_t)r * N + cc) = h01;
                *(uint32_t*)(Cl + (size_t)r * N + cc) = l01;
                *(uint32_t*)(Ch + (size_t)(r + 8) * N + cc) = h23;
                *(uint32_t*)(Cl + (size_t)(r + 8) * N + cc) = l23;
            } else {
                if (EPI == 1) {
                    const float* rp0 = Res + (size_t)r * N + cc;
                    const float* rp1 = Res + (size_t)(r + 8) * N + cc;
                    v0 += rp0[0]; v1 += rp0[1];
                    v2 += rp1[0]; v3 += rp1[1];
                }
                *reinterpret_cast<float2*>(C + (size_t)r * N + cc) = make_float2(v0, v1);
                *reinterpret_cast<float2*>(C + (size_t)(r + 8) * N + cc) = make_float2(v2, v3);
            }
        }
    }
}

// ================= fused causal flash attention =============================
// CTA = (q-tile of 128 rows, bh). Q staged once; KV streamed in 64-row tiles;
// online softmax in fp32; P via smem; O accum in regs; bf16-split output.
// Thread map: tx=tid&15 (4 kv cols / 4 d cols), ty=tid>>4 (8 q rows).

#define FL_QS 0
#define FL_KS (64*132)
#define FL_VS (FL_KS + 64*68)
#define FL_PS (FL_VS + 64*68)
#define FL_SMEM ((FL_PS + 128*68)*4)   // floats -> bytes

__global__ __launch_bounds__(256, 2) void flash_kernel() {
    extern __shared__ float fs[];
    int bh = blockIdx.y;
    int b = bh / NH, h = bh % NH;
    int t0 = blockIdx.x * 128;
    const float* qb = g_qkv + (size_t)b * SEQ * QKVN + h * DH;
    const float* kb = qb + EMB;
    const float* vb = qb + 2 * EMB;
    int tid = threadIdx.x;
    int tx = tid & 15, ty = tid >> 4;

    // stage Q tile transposed: Qs[d][q], pad 132
    {
        int q = tid >> 1, d0 = (tid & 1) * 32;
        const float* qp = qb + (size_t)(t0 + q) * QKVN + d0;
#pragma unroll
        for (int i = 0; i < 8; i++) {
            float4 v = *reinterpret_cast<const float4*>(qp + 4 * i);
            int d = d0 + 4 * i;
            fs[FL_QS + (d + 0) * 132 + q] = v.x;
            fs[FL_QS + (d + 1) * 132 + q] = v.y;
            fs[FL_QS + (d + 2) * 132 + q] = v.z;
            fs[FL_QS + (d + 3) * 132 + q] = v.w;
        }
    }

    float m[8], l[8], O[8][4];
#pragma unroll
    for (int i = 0; i < 8; i++) {
        m[i] = -1e30f; l[i] = 0.f;
#pragma unroll
        for (int d = 0; d < 4; d++) O[i][d] = 0.f;
    }

    int ntile = (t0 >> 6) + 2;
    for (int j = 0; j < ntile; j++) {
        __syncthreads();   // guard K/V/P reuse
        // load K tile (transposed -> Ks[d][s], pad 68) and V tile (Vs[s][d], pad 68)
        {
            int s = tid >> 2;
            const float* kp = kb + (size_t)(j * 64 + s) * QKVN;
            const float* vp = vb + (size_t)(j * 64 + s) * QKVN;
#pragma unroll
            for (int i = 0; i < 4; i++) {
                int d0 = (tid & 3) * 16 + i * 4;
                float4 kv = *reinterpret_cast<const float4*>(kp + d0);
                fs[FL_KS + (d0 + 0) * 68 + s] = kv.x;
                fs[FL_KS + (d0 + 1) * 68 + s] = kv.y;
                fs[FL_KS + (d0 + 2) * 68 + s] = kv.z;
                fs[FL_KS + (d0 + 3) * 68 + s] = kv.w;
                float4 vv = *reinterpret_cast<const float4*>(vp + d0);
                *reinterpret_cast<float4*>(fs + FL_VS + s * 68 + d0) = vv;
            }
        }
        __syncthreads();

        // S = scale * Q K^T (128 x 64), thread: 8 q x 4 kv
        float S[8][4];
#pragma unroll
        for (int i = 0; i < 8; i++)
#pragma unroll
            for (int q = 0; q < 4; q++) S[i][q] = 0.f;
#pragma unroll 4
        for (int kk = 0; kk < 64; kk++) {
            float4 a0 = *reinterpret_cast<const float4*>(fs + FL_QS + kk * 132 + ty * 8);
            float4 a1 = *reinterpret_cast<const float4*>(fs + FL_QS + kk * 132 + ty * 8 + 4);
            float4 bv = *reinterpret_cast<const float4*>(fs + FL_KS + kk * 68 + tx * 4);
            float a[8] = {a0.x, a0.y, a0.z, a0.w, a1.x, a1.y, a1.z, a1.w};
            float bb[4] = {bv.x, bv.y, bv.z, bv.w};
#pragma unroll
            for (int i = 0; i < 8; i++)
#pragma unroll
                for (int q = 0; q < 4; q++)
                    S[i][q] = fmaf(a[i], bb[q], S[i][q]);
        }

        // mask + scale + online softmax update
#pragma unroll
        for (int i = 0; i < 8; i++) {
            int t = t0 + ty * 8 + i;
            int s0 = j * 64 + tx * 4;
#pragma unroll
            for (int q = 0; q < 4; q++) {
                S[i][q] *= 0.125f;
                if (s0 + q > t) S[i][q] = -1e30f;
            }
            float mx = fmaxf(fmaxf(S[i][0], S[i][1]), fmaxf(S[i][2], S[i][3]));
#pragma unroll
            for (int o = 1; o < 16; o <<= 1)
                mx = fmaxf(mx, __shfl_xor_sync(0xffffffffu, mx, o));
            float mn = fmaxf(m[i], mx);
            float c = __expf(m[i] - mn);
            m[i] = mn;
            float rs = 0.f;
#pragma unroll
            for (int q = 0; q < 4; q++) {
                S[i][q] = __expf(S[i][q] - mn);
                rs += S[i][q];
            }
#pragma unroll
            for (int o = 1; o < 16; o <<= 1)
                rs += __shfl_xor_sync(0xffffffffu, rs, o);
            l[i] = l[i] * c + rs;
#pragma unroll
            for (int d = 0; d < 4; d++) O[i][d] *= c;
            *reinterpret_cast<float4*>(fs + FL_PS + (ty * 8 + i) * 68 + tx * 4)
                = make_float4(S[i][0], S[i][1], S[i][2], S[i][3]);
        }
        __syncthreads();

        // O += P V  (thread: 8 q x 4 d, d cols = tx*4)
#pragma unroll 4
        for (int kv = 0; kv < 64; kv++) {
            float4 bv = *reinterpret_cast<const float4*>(fs + FL_VS + kv * 68 + tx * 4);
#pragma unroll
            for (int i = 0; i < 8; i++) {
                float a = fs[FL_PS + (ty * 8 + i) * 68 + kv];
                O[i][0] = fmaf(a, bv.x, O[i][0]);
                O[i][1] = fmaf(a, bv.y, O[i][1]);
                O[i][2] = fmaf(a, bv.z, O[i][2]);
                O[i][3] = fmaf(a, bv.w, O[i][3]);
            }
        }
    }

    // write O / l as bf16 hi/lo
#pragma unroll
    for (int i = 0; i < 8; i++) {
        int t = t0 + ty * 8 + i;
        float inv = 1.f / l[i];
        size_t base = (size_t)(b * SEQ + t) * EMB + h * DH + tx * 4;
        uint32_t h01, l01, h23, l23;
        cvt_split2(O[i][0] * inv, O[i][1] * inv, h01, l01);
        cvt_split2(O[i][2] * inv, O[i][3] * inv, h23, l23);
        *(uint32_t*)(g_atth + base)     = h01;
        *(uint32_t*)(g_attl + base)     = l01;
        *(uint32_t*)(g_atth + base + 2) = h23;
        *(uint32_t*)(g_attl + base + 2) = l23;
    }
}

// ---------------- head GEMM (N=60, FFMA) ----------------
__global__ __launch_bounds__(256) void head_gemm_kernel(
    const float* __restrict__ A,
    const float* __restrict__ Bm,
    const float* __restrict__ bias,
    float* __restrict__ C,
    int N, int K)
{
    __shared__ float As[16][68];
    __shared__ float Bs[16][64];
    int m0 = blockIdx.y * 64, n0 = blockIdx.x * 64;
    int tid = threadIdx.x;
    int tx = tid & 15, ty = tid >> 4;
    float acc[4][4] = {};
    for (int k0 = 0; k0 < K; k0 += 16) {
#pragma unroll
        for (int i = 0; i < 4; i++) {
            int lin = tid + i * 256;
            int r = lin >> 4, c = lin & 15;
            As[c][r] = A[(size_t)(m0 + r) * K + k0 + c];
        }
#pragma unroll
        for (int i = 0; i < 4; i++) {
            int lin = tid + i * 256;
            int r = lin >> 6, c = lin & 63;
            int n = n0 + c;
            Bs[r][c] = (n < N) ? Bm[(size_t)(k0 + r) * N + n] : 0.f;
        }
        __syncthreads();
#pragma unroll
        for (int kk = 0; kk < 16; kk++) {
            float4 a4 = *reinterpret_cast<const float4*>(&As[kk][ty * 4]);
            float4 b4 = *reinterpret_cast<const float4*>(&Bs[kk][tx * 4]);
            float a[4] = {a4.x, a4.y, a4.z, a4.w};
            float bv[4] = {b4.x, b4.y, b4.z, b4.w};
#pragma unroll
            for (int i = 0; i < 4; i++)
#pragma unroll
                for (int j = 0; j < 4; j++)
                    acc[i][j] = fmaf(a[i], bv[j], acc[i][j]);
        }
        __syncthreads();
    }
#pragma unroll
    for (int i = 0; i < 4; i++) {
        int m = m0 + ty * 4 + i;
#pragma unroll
        for (int j = 0; j < 4; j++) {
            int n = n0 + tx * 4 + j;
            if (n < N) C[(size_t)m * N + n] = acc[i][j] + bias[n];
        }
    }
}

// ---------------- host orchestration ----------------
extern "C" void kernel_launch(void* const* d_in, const int* in_sizes, int n_in,
                              void* d_out, int out_size) {
    const int*   ids          = (const int*)d_in[0];
    const int*   mul          = (const int*)d_in[1];
    const float* tok_emb      = (const float*)d_in[2];
    const float* state_emb    = (const float*)d_in[3];
    const float* state_proj_w = (const float*)d_in[4];
    const float* state_proj_b = (const float*)d_in[5];
    const float* wpe          = (const float*)d_in[6];
    const float* ln1_g        = (const float*)d_in[7];
    const float* ln1_b        = (const float*)d_in[8];
    const float* attn_w       = (const float*)d_in[9];
    const float* attn_b       = (const float*)d_in[10];
    const float* attn_proj_w  = (const float*)d_in[11];
    const float* attn_proj_b  = (const float*)d_in[12];
    const float* ln2_g        = (const float*)d_in[13];
    const float* ln2_b        = (const float*)d_in[14];
    const float* fc_w         = (const float*)d_in[15];
    const float* fc_b         = (const float*)d_in[16];
    const float* mlp_proj_w   = (const float*)d_in[17];
    const float* mlp_proj_b   = (const float*)d_in[18];
    const float* lnf_g        = (const float*)d_in[19];
    const float* lnf_b        = (const float*)d_in[20];
    const float* head_w       = (const float*)d_in[21];
    const float* head_b       = (const float*)d_in[22];
    float* out = (float*)d_out;

    float *h, *lnbuf, *qkv;
    __nv_bfloat16 *wh, *wl, *lnh, *lnl, *atth, *attl, *midh, *midl;
    cudaGetSymbolAddress((void**)&h,     g_h);
    cudaGetSymbolAddress((void**)&lnbuf, g_ln);
    cudaGetSymbolAddress((void**)&qkv,   g_qkv);
    cudaGetSymbolAddress((void**)&wh,    g_wh);
    cudaGetSymbolAddress((void**)&wl,    g_wl);
    cudaGetSymbolAddress((void**)&lnh,   g_lnh);
    cudaGetSymbolAddress((void**)&lnl,   g_lnl);
    cudaGetSymbolAddress((void**)&atth,  g_atth);
    cudaGetSymbolAddress((void**)&attl,  g_attl);
    cudaGetSymbolAddress((void**)&midh,  g_midh);
    cudaGetSymbolAddress((void**)&midl,  g_midl);

    cudaFuncSetAttribute(mma_gemm<0>, cudaFuncAttributeMaxDynamicSharedMemorySize, GEMM_SMEM);
    cudaFuncSetAttribute(mma_gemm<1>, cudaFuncAttributeMaxDynamicSharedMemorySize, GEMM_SMEM);
    cudaFuncSetAttribute(mma_gemm<2>, cudaFuncAttributeMaxDynamicSharedMemorySize, GEMM_SMEM);
    cudaFuncSetAttribute(flash_kernel, cudaFuncAttributeMaxDynamicSharedMemorySize, FL_SMEM);

    wconv_kernel<<<dim3(QKVN/32, EMB/32, NLAYER), 256>>>(attn_w, wh + OFF_QKV, wl + OFF_QKV, EMB, QKVN);
    wconv_kernel<<<dim3(EMB/32, EMB/32, NLAYER), 256>>>(attn_proj_w, wh + OFF_PROJ, wl + OFF_PROJ, EMB, EMB);
    wconv_kernel<<<dim3(FFN/32, EMB/32, NLAYER), 256>>>(fc_w, wh + OFF_FC, wl + OFF_FC, EMB, FFN);
    wconv_kernel<<<dim3(EMB/32, FFN/32, NLAYER), 256>>>(mlp_proj_w, wh + OFF_MLP, wl + OFF_MLP, FFN, EMB);

    state_scan_kernel<<<1, 256>>>(ids, mul);
    state_proj_kernel<<<(VOC * EMB + 255) / 256, 256>>>(state_emb, state_proj_w, state_proj_b);
    embed_kernel<<<(BT * EMB + 255) / 256, 256>>>(ids, tok_emb, wpe);

    for (int l = 0; l < NLAYER; l++) {
        ln_bf16_kernel<<<BT, 256>>>(h, ln1_g + l * EMB, ln1_b + l * EMB, lnh, lnl);
        mma_gemm<0><<<dim3(QKVN/64, BT/128), 256, GEMM_SMEM>>>(
            lnh, lnl, wh + OFF_QKV + (size_t)l * W_QKV, wl + OFF_QKV + (size_t)l * W_QKV,
            attn_b + l * QKVN, nullptr, qkv, nullptr, nullptr, EMB, QKVN);
        flash_kernel<<<dim3(SEQ/128, BATCH * NH), 256, FL_SMEM>>>();
        mma_gemm<1><<<dim3(EMB/64, BT/128), 256, GEMM_SMEM>>>(
            atth, attl, wh + OFF_PROJ + (size_t)l * W_PROJ, wl + OFF_PROJ + (size_t)l * W_PROJ,
            attn_proj_b + l * EMB, h, h, nullptr, nullptr, EMB, EMB);
        ln_bf16_kernel<<<BT, 256>>>(h, ln2_g + l * EMB, ln2_b + l * EMB, lnh, lnl);
        mma_gemm<2><<<dim3(FFN/64, BT/128), 256, GEMM_SMEM>>>(
            lnh, lnl, wh + OFF_FC + (size_t)l * W_FC, wl + OFF_FC + (size_t)l * W_FC,
            fc_b + l * FFN, nullptr, nullptr, midh, midl, EMB, FFN);
        mma_gemm<1><<<dim3(EMB/64, BT/128), 256, GEMM_SMEM>>>(
            midh, midl, wh + OFF_MLP + (size_t)l * W_MLP, wl + OFF_MLP + (size_t)l * W_MLP,
            mlp_proj_b + l * EMB, h, h, nullptr, nullptr, FFN, EMB);
    }

    ln_kernel<<<BT, 256>>>(h, lnf_g, lnf_b, lnbuf);
    head_gemm_kernel<<<dim3(1, BT / 64), 256>>>(lnbuf, head_w, head_b, out, VOC, EMB);
}

// round 7
// speedup vs baseline: 2.8130x; 1.1557x over previous
#include <cuda_runtime.h>
#include <cuda_fp16.h>
#include <math.h>
#include <stdint.h>

#define BATCH 8
#define SEQ 512
#define BT (BATCH*SEQ)        // 4096
#define EMB 768
#define NH 12
#define DH 64
#define VOC 60
#define DST 128
#define NLAYER 12
#define QKVN (3*EMB)          // 2304
#define FFN (4*EMB)           // 3072

#define W_QKV (QKVN*EMB)
#define W_PROJ (EMB*EMB)
#define W_FC (FFN*EMB)
#define W_MLP (EMB*FFN)
#define OFF_QKV 0
#define OFF_PROJ (12*W_QKV)
#define OFF_FC (OFF_PROJ + 12*W_PROJ)
#define OFF_MLP (OFF_FC + 12*W_FC)
#define W_TOTAL (OFF_MLP + 12*W_MLP)

// ---------------- scratch ----------------
__device__ float g_h[BT*EMB];
__device__ float g_ln[BT*EMB];
__device__ float g_qkv[BT*QKVN];
__device__ float g_semb[VOC*EMB];
__device__ int   g_pre[BT];

__device__ __half g_wh[W_TOTAL];                 // weights, single fp16, [N][K]
__device__ __half g_lnh[BT*EMB],  g_lnl[BT*EMB]; // activations, fp16 hi/lo
__device__ __half g_atth[BT*EMB], g_attl[BT*EMB];
__device__ __half g_midh[BT*FFN], g_midl[BT*FFN];

// ---------------- helpers ----------------
__device__ __forceinline__ uint32_t smem_u32(const void* p) {
    uint32_t a;
    asm("{ .reg .u64 t; cvta.to.shared.u64 t, %1; cvt.u32.u64 %0, t; }" : "=r"(a) : "l"(p));
    return a;
}

__device__ __forceinline__ void ldsm_x4(uint32_t* r, uint32_t addr) {
    asm volatile("ldmatrix.sync.aligned.m8n8.x4.shared.b16 {%0,%1,%2,%3}, [%4];"
        : "=r"(r[0]), "=r"(r[1]), "=r"(r[2]), "=r"(r[3]) : "r"(addr));
}

__device__ __forceinline__ void mma_f16(float* c, const uint32_t* a, const uint32_t* b) {
    asm volatile("mma.sync.aligned.m16n8k16.row.col.f32.f16.f16.f32 "
        "{%0,%1,%2,%3}, {%4,%5,%6,%7}, {%8,%9}, {%0,%1,%2,%3};"
        : "+f"(c[0]), "+f"(c[1]), "+f"(c[2]), "+f"(c[3])
        : "r"(a[0]), "r"(a[1]), "r"(a[2]), "r"(a[3]), "r"(b[0]), "r"(b[1]));
}

__device__ __forceinline__ void cp16(uint32_t dst, const void* src) {
    asm volatile("cp.async.cg.shared.global [%0], [%1], 16;" :: "r"(dst), "l"(src));
}
#define CP_COMMIT() asm volatile("cp.async.commit_group;" ::: "memory")
#define CP_WAIT(n)  asm volatile("cp.async.wait_group %0;" :: "n"(n) : "memory")

// fp16 two-term split of a pair of fp32 values
__device__ __forceinline__ void cvt_split2h(float x0, float x1, uint32_t& hi, uint32_t& lo) {
    __half h0 = __float2half_rn(x0);
    __half h1 = __float2half_rn(x1);
    __half l0 = __float2half_rn(x0 - __half2float(h0));
    __half l1 = __float2half_rn(x1 - __half2float(h1));
    __half2 H(h0, h1), L(l0, l1);
    hi = *(uint32_t*)&H;
    lo = *(uint32_t*)&L;
}

// ---------------- reductions ----------------
__device__ __forceinline__ float breduce_sum(float v, float* sh, int nthr) {
#pragma unroll
    for (int o = 16; o > 0; o >>= 1) v += __shfl_xor_sync(0xffffffffu, v, o);
    int lane = threadIdx.x & 31, w = threadIdx.x >> 5;
    if (lane == 0) sh[w] = v;
    __syncthreads();
    float r = 0.f;
    if ((int)threadIdx.x < (nthr >> 5)) r = sh[threadIdx.x];
    if (threadIdx.x < 32) {
#pragma unroll
        for (int o = 16; o > 0; o >>= 1) r += __shfl_xor_sync(0xffffffffu, r, o);
        if (threadIdx.x == 0) sh[0] = r;
    }
    __syncthreads();
    r = sh[0];
    __syncthreads();
    return r;
}

// ---------------- automaton state scan ----------------
__global__ void state_scan_kernel(const int* __restrict__ ids, const int* __restrict__ mul) {
    __shared__ int smul[VOC*VOC];
    __shared__ int sids[BT];
    int tid = threadIdx.x;
    for (int i = tid; i < VOC*VOC; i += blockDim.x) smul[i] = mul[i];
    for (int i = tid; i < BT; i += blockDim.x) sids[i] = ids[i];
    __syncthreads();
    if (tid < BATCH) {
        int s = 0;
        const int* row = sids + tid * SEQ;
        int* pre = g_pre + tid * SEQ;
        for (int t = 0; t < SEQ; t++) {
            pre[t] = s;
            s = smul[row[t] * VOC + s];
        }
    }
}

__global__ void state_proj_kernel(const float* __restrict__ semb,
                                  const float* __restrict__ W,
                                  const float* __restrict__ b) {
    int idx = blockIdx.x * blockDim.x + threadIdx.x;
    if (idx >= VOC * EMB) return;
    int v = idx / EMB, e = idx % EMB;
    float acc = b[e];
#pragma unroll 8
    for (int d = 0; d < DST; d++) acc += semb[v * DST + d] * W[d * EMB + e];
    g_semb[idx] = acc;
}

__global__ void embed_kernel(const int* __restrict__ ids,
                             const float* __restrict__ tok_emb,
                             const float* __restrict__ wpe) {
    int idx = blockIdx.x * blockDim.x + threadIdx.x;
    if (idx >= BT * EMB) return;
    int bt = idx / EMB, e = idx % EMB;
    int t = bt % SEQ;
    g_h[idx] = tok_emb[ids[bt] * EMB + e] + g_semb[g_pre[bt] * EMB + e] + wpe[t * EMB + e];
}

// ---------------- weight convert: W[K][N] fp32 -> fp16 [N][K] --------------
__global__ __launch_bounds__(256) void wconv_kernel(
    const float* __restrict__ W, __half* __restrict__ Hi, int K, int N)
{
    __shared__ float t[32][33];
    int l = blockIdx.z;
    const float* Wl = W + (size_t)l * K * N;
    __half* Hl = Hi + (size_t)l * K * N;
    int n0 = blockIdx.x * 32, k0 = blockIdx.y * 32;
    int tx = threadIdx.x & 31, ty = threadIdx.x >> 5;
#pragma unroll
    for (int j = 0; j < 4; j++)
        t[ty + 8 * j][tx] = Wl[(size_t)(k0 + ty + 8 * j) * N + n0 + tx];
    __syncthreads();
#pragma unroll
    for (int j = 0; j < 4; j++) {
        float v = t[tx][ty + 8 * j];
        Hl[(size_t)(n0 + ty + 8 * j) * K + k0 + tx] = __float2half_rn(v);
    }
}

// ---------------- layernorm variants ----------------
__global__ __launch_bounds__(256) void ln_kernel(const float* __restrict__ x,
                                                 const float* __restrict__ g,
                                                 const float* __restrict__ b,
                                                 float* __restrict__ y) {
    __shared__ float sh[8];
    int row = blockIdx.x, tid = threadIdx.x;
    const float* xr = x + (size_t)row * EMB;
    float v0 = xr[tid], v1 = xr[tid + 256], v2 = xr[tid + 512];
    float mean = breduce_sum(v0 + v1 + v2, sh, 256) * (1.f / EMB);
    float d0 = v0 - mean, d1 = v1 - mean, d2 = v2 - mean;
    float var = breduce_sum(d0*d0 + d1*d1 + d2*d2, sh, 256) * (1.f / EMB);
    float rstd = rsqrtf(var + 1e-5f);
    float* yr = y + (size_t)row * EMB;
    yr[tid]       = d0 * rstd * g[tid]       + b[tid];
    yr[tid + 256] = d1 * rstd * g[tid + 256] + b[tid + 256];
    yr[tid + 512] = d2 * rstd * g[tid + 512] + b[tid + 512];
}

__global__ __launch_bounds__(256) void ln_f16_kernel(const float* __restrict__ x,
                                                     const float* __restrict__ g,
                                                     const float* __restrict__ b,
                                                     __half* __restrict__ yh,
                                                     __half* __restrict__ yl) {
    __shared__ float sh[8];
    int row = blockIdx.x, tid = threadIdx.x;
    const float* xr = x + (size_t)row * EMB;
    float v0 = xr[tid], v1 = xr[tid + 256], v2 = xr[tid + 512];
    float mean = breduce_sum(v0 + v1 + v2, sh, 256) * (1.f / EMB);
    float d0 = v0 - mean, d1 = v1 - mean, d2 = v2 - mean;
    float var = breduce_sum(d0*d0 + d1*d1 + d2*d2, sh, 256) * (1.f / EMB);
    float rstd = rsqrtf(var + 1e-5f);
    size_t base = (size_t)row * EMB;
#pragma unroll
    for (int q = 0; q < 3; q++) {
        int e = tid + q * 256;
        float d = (q == 0) ? d0 : (q == 1) ? d1 : d2;
        float v = d * rstd * g[e] + b[e];
        __half h = __float2half_rn(v);
        yh[base + e] = h;
        yl[base + e] = __float2half_rn(v - __half2float(h));
    }
}

// ================= mma.sync fp16 2-term GEMM (2 CTAs/SM) ===================
// C = epi((Ah+Al) @ Bh^T + bias); A fp16 hi/lo [M][K]; B fp16 [N][K].
// CTA 128x64, 8 warps 4(M)x2(N), warp tile 32x32, K-chunk 32.
// 2 MMAs per fragment pair: Ah*Bh + Al*Bh.

__device__ __forceinline__ float gelu_f(float x) {
    return 0.5f * x * (1.f + tanhf(0.7978845608028654f * (x + 0.044715f * x * x * x)));
}

#define ROWB 80
#define SM_AH 0
#define SM_AL 10240
#define SM_BH 20480
#define BUFSZ 25600
#define GEMM_SMEM (2*BUFSZ)   // 51200

template<int EPI>
__global__ __launch_bounds__(256, 2) void mma_gemm(
    const __half* __restrict__ Ah, const __half* __restrict__ Al,
    const __half* __restrict__ Bh,
    const float* __restrict__ bias,
    const float* __restrict__ Res,
    float* __restrict__ C,
    __half* __restrict__ Ch, __half* __restrict__ Cl,
    int K, int N)
{
    extern __shared__ __align__(16) char sm[];
    uint32_t sb = smem_u32(sm);
    int tid = threadIdx.x;
    int wid = tid >> 5, lane = tid & 31;
    int wm = wid & 3, wn = wid >> 2;
    int m0 = blockIdx.y * 128, n0 = blockIdx.x * 64;

    int p_row = tid >> 2;
    int p_seg = tid & 3;

    int a_row = lane & 15;
    int a_colb = ((lane >> 4) * 8) * 2;
    int b_row = (lane & 7) + ((lane >> 4) & 1) * 8;
    int b_colb = (((lane >> 3) & 1) * 8) * 2;

    float acc[2][4][4];
#pragma unroll
    for (int i = 0; i < 2; i++)
#pragma unroll
        for (int j = 0; j < 4; j++)
#pragma unroll
            for (int q = 0; q < 4; q++) acc[i][j][q] = 0.f;

    const int nch = K >> 5;

    auto issue = [&](int c, int bufsel) {
        int k0 = c << 5;
        uint32_t base = sb + bufsel * BUFSZ;
        uint32_t doff = (uint32_t)(p_row * ROWB + p_seg * 16);
#pragma unroll
        for (int i = 0; i < 2; i++) {
            int row = p_row + i * 64;
            size_t aoff = (size_t)(m0 + row) * K + k0 + p_seg * 8;
            cp16(base + SM_AH + doff + i * (64 * ROWB), Ah + aoff);
            cp16(base + SM_AL + doff + i * (64 * ROWB), Al + aoff);
        }
        size_t boff = (size_t)(n0 + p_row) * K + k0 + p_seg * 8;
        cp16(base + SM_BH + doff, Bh + boff);
    };

    issue(0, 0);
    CP_COMMIT();

    for (int c = 0; c < nch; c++) {
        int cur = c & 1;
        if (c + 1 < nch) {
            issue(c + 1, cur ^ 1);
            CP_COMMIT();
            CP_WAIT(1);
        } else {
            CP_WAIT(0);
        }
        __syncthreads();

        uint32_t base = sb + cur * BUFSZ;
#pragma unroll
        for (int ks = 0; ks < 2; ks++) {
            uint32_t a_hi[2][4], a_lo[2][4];
#pragma unroll
            for (int mt = 0; mt < 2; mt++) {
                uint32_t off = (uint32_t)((wm * 32 + mt * 16 + a_row) * ROWB
                                          + ks * 32 + a_colb);
                ldsm_x4(a_hi[mt], base + SM_AH + off);
                ldsm_x4(a_lo[mt], base + SM_AL + off);
            }
            uint32_t b_hi[2][4];
#pragma unroll
            for (int p = 0; p < 2; p++) {
                uint32_t off = (uint32_t)((wn * 32 + p * 16 + b_row) * ROWB
                                          + ks * 32 + b_colb);
                ldsm_x4(b_hi[p], base + SM_BH + off);
            }
#pragma unroll
            for (int mt = 0; mt < 2; mt++)
#pragma unroll
                for (int p = 0; p < 2; p++) {
                    mma_f16(acc[mt][2*p],   a_hi[mt], &b_hi[p][0]);
                    mma_f16(acc[mt][2*p+1], a_hi[mt], &b_hi[p][2]);
                }
#pragma unroll
            for (int mt = 0; mt < 2; mt++)
#pragma unroll
                for (int p = 0; p < 2; p++) {
                    mma_f16(acc[mt][2*p],   a_lo[mt], &b_hi[p][0]);
                    mma_f16(acc[mt][2*p+1], a_lo[mt], &b_hi[p][2]);
                }
        }
        __syncthreads();
    }

    int r0 = m0 + wm * 32 + (lane >> 2);
    int c0 = n0 + wn * 32 + (lane & 3) * 2;
#pragma unroll
    for (int mt = 0; mt < 2; mt++) {
#pragma unroll
        for (int nt = 0; nt < 4; nt++) {
            int r = r0 + mt * 16;
            int cc = c0 + nt * 8;
            float b0 = bias[cc], b1 = bias[cc + 1];
            float v0 = acc[mt][nt][0] + b0;
            float v1 = acc[mt][nt][1] + b1;
            float v2 = acc[mt][nt][2] + b0;
            float v3 = acc[mt][nt][3] + b1;
            if (EPI == 2) {
                v0 = gelu_f(v0); v1 = gelu_f(v1);
                v2 = gelu_f(v2); v3 = gelu_f(v3);
                uint32_t h01, l01, h23, l23;
                cvt_split2h(v0, v1, h01, l01);
                cvt_split2h(v2, v3, h23, l23);
                *(uint32_t*)(Ch + (size_t)r * N + cc) = h01;
                *(uint32_t*)(Cl + (size_t)r * N + cc) = l01;
                *(uint32_t*)(Ch + (size_t)(r + 8) * N + cc) = h23;
                *(uint32_t*)(Cl + (size_t)(r + 8) * N + cc) = l23;
            } else {
                if (EPI == 1) {
                    const float* rp0 = Res + (size_t)r * N + cc;
                    const float* rp1 = Res + (size_t)(r + 8) * N + cc;
                    v0 += rp0[0]; v1 += rp0[1];
                    v2 += rp1[0]; v3 += rp1[1];
                }
                *reinterpret_cast<float2*>(C + (size_t)r * N + cc) = make_float2(v0, v1);
                *reinterpret_cast<float2*>(C + (size_t)(r + 8) * N + cc) = make_float2(v2, v3);
            }
        }
    }
}

// ================= fused causal flash attention =============================
#define FL_QS 0
#define FL_KS (64*132)
#define FL_VS (FL_KS + 64*68)
#define FL_PS (FL_VS + 64*68)
#define FL_SMEM ((FL_PS + 128*68)*4)

__global__ __launch_bounds__(256, 2) void flash_kernel() {
    extern __shared__ float fs[];
    int bh = blockIdx.y;
    int b = bh / NH, h = bh % NH;
    int t0 = blockIdx.x * 128;
    const float* qb = g_qkv + (size_t)b * SEQ * QKVN + h * DH;
    const float* kb = qb + EMB;
    const float* vb = qb + 2 * EMB;
    int tid = threadIdx.x;
    int tx = tid & 15, ty = tid >> 4;

    {
        int q = tid >> 1, d0 = (tid & 1) * 32;
        const float* qp = qb + (size_t)(t0 + q) * QKVN + d0;
#pragma unroll
        for (int i = 0; i < 8; i++) {
            float4 v = *reinterpret_cast<const float4*>(qp + 4 * i);
            int d = d0 + 4 * i;
            fs[FL_QS + (d + 0) * 132 + q] = v.x;
            fs[FL_QS + (d + 1) * 132 + q] = v.y;
            fs[FL_QS + (d + 2) * 132 + q] = v.z;
            fs[FL_QS + (d + 3) * 132 + q] = v.w;
        }
    }

    float m[8], l[8], O[8][4];
#pragma unroll
    for (int i = 0; i < 8; i++) {
        m[i] = -1e30f; l[i] = 0.f;
#pragma unroll
        for (int d = 0; d < 4; d++) O[i][d] = 0.f;
    }

    int ntile = (t0 >> 6) + 2;
    for (int j = 0; j < ntile; j++) {
        __syncthreads();
        {
            int s = tid >> 2;
            const float* kp = kb + (size_t)(j * 64 + s) * QKVN;
            const float* vp = vb + (size_t)(j * 64 + s) * QKVN;
#pragma unroll
            for (int i = 0; i < 4; i++) {
                int d0 = (tid & 3) * 16 + i * 4;
                float4 kv = *reinterpret_cast<const float4*>(kp + d0);
                fs[FL_KS + (d0 + 0) * 68 + s] = kv.x;
                fs[FL_KS + (d0 + 1) * 68 + s] = kv.y;
                fs[FL_KS + (d0 + 2) * 68 + s] = kv.z;
                fs[FL_KS + (d0 + 3) * 68 + s] = kv.w;
                float4 vv = *reinterpret_cast<const float4*>(vp + d0);
                *reinterpret_cast<float4*>(fs + FL_VS + s * 68 + d0) = vv;
            }
        }
        __syncthreads();

        float S[8][4];
#pragma unroll
        for (int i = 0; i < 8; i++)
#pragma unroll
            for (int q = 0; q < 4; q++) S[i][q] = 0.f;
#pragma unroll 4
        for (int kk = 0; kk < 64; kk++) {
            float4 a0 = *reinterpret_cast<const float4*>(fs + FL_QS + kk * 132 + ty * 8);
            float4 a1 = *reinterpret_cast<const float4*>(fs + FL_QS + kk * 132 + ty * 8 + 4);
            float4 bv = *reinterpret_cast<const float4*>(fs + FL_KS + kk * 68 + tx * 4);
            float a[8] = {a0.x, a0.y, a0.z, a0.w, a1.x, a1.y, a1.z, a1.w};
            float bb[4] = {bv.x, bv.y, bv.z, bv.w};
#pragma unroll
            for (int i = 0; i < 8; i++)
#pragma unroll
                for (int q = 0; q < 4; q++)
                    S[i][q] = fmaf(a[i], bb[q], S[i][q]);
        }

#pragma unroll
        for (int i = 0; i < 8; i++) {
            int t = t0 + ty * 8 + i;
            int s0 = j * 64 + tx * 4;
#pragma unroll
            for (int q = 0; q < 4; q++) {
                S[i][q] *= 0.125f;
                if (s0 + q > t) S[i][q] = -1e30f;
            }
            float mx = fmaxf(fmaxf(S[i][0], S[i][1]), fmaxf(S[i][2], S[i][3]));
#pragma unroll
            for (int o = 1; o < 16; o <<= 1)
                mx = fmaxf(mx, __shfl_xor_sync(0xffffffffu, mx, o));
            float mn = fmaxf(m[i], mx);
            float c = __expf(m[i] - mn);
            m[i] = mn;
            float rs = 0.f;
#pragma unroll
            for (int q = 0; q < 4; q++) {
                S[i][q] = __expf(S[i][q] - mn);
                rs += S[i][q];
            }
#pragma unroll
            for (int o = 1; o < 16; o <<= 1)
                rs += __shfl_xor_sync(0xffffffffu, rs, o);
            l[i] = l[i] * c + rs;
#pragma unroll
            for (int d = 0; d < 4; d++) O[i][d] *= c;
            *reinterpret_cast<float4*>(fs + FL_PS + (ty * 8 + i) * 68 + tx * 4)
                = make_float4(S[i][0], S[i][1], S[i][2], S[i][3]);
        }
        __syncthreads();

#pragma unroll 4
        for (int kv = 0; kv < 64; kv++) {
            float4 bv = *reinterpret_cast<const float4*>(fs + FL_VS + kv * 68 + tx * 4);
#pragma unroll
            for (int i = 0; i < 8; i++) {
                float a = fs[FL_PS + (ty * 8 + i) * 68 + kv];
                O[i][0] = fmaf(a, bv.x, O[i][0]);
                O[i][1] = fmaf(a, bv.y, O[i][1]);
                O[i][2] = fmaf(a, bv.z, O[i][2]);
                O[i][3] = fmaf(a, bv.w, O[i][3]);
            }
        }
    }

#pragma unroll
    for (int i = 0; i < 8; i++) {
        int t = t0 + ty * 8 + i;
        float inv = 1.f / l[i];
        size_t base = (size_t)(b * SEQ + t) * EMB + h * DH + tx * 4;
        uint32_t h01, l01, h23, l23;
        cvt_split2h(O[i][0] * inv, O[i][1] * inv, h01, l01);
        cvt_split2h(O[i][2] * inv, O[i][3] * inv, h23, l23);
        *(uint32_t*)(g_atth + base)     = h01;
        *(uint32_t*)(g_attl + base)     = l01;
        *(uint32_t*)(g_atth + base + 2) = h23;
        *(uint32_t*)(g_attl + base + 2) = l23;
    }
}

// ---------------- head GEMM (N=60, FFMA) ----------------
__global__ __launch_bounds__(256) void head_gemm_kernel(
    const float* __restrict__ A,
    const float* __restrict__ Bm,
    const float* __restrict__ bias,
    float* __restrict__ C,
    int N, int K)
{
    __shared__ float As[16][68];
    __shared__ float Bs[16][64];
    int m0 = blockIdx.y * 64, n0 = blockIdx.x * 64;
    int tid = threadIdx.x;
    int tx = tid & 15, ty = tid >> 4;
    float acc[4][4] = {};
    for (int k0 = 0; k0 < K; k0 += 16) {
#pragma unroll
        for (int i = 0; i < 4; i++) {
            int lin = tid + i * 256;
            int r = lin >> 4, c = lin & 15;
            As[c][r] = A[(size_t)(m0 + r) * K + k0 + c];
        }
#pragma unroll
        for (int i = 0; i < 4; i++) {
            int lin = tid + i * 256;
            int r = lin >> 6, c = lin & 63;
            int n = n0 + c;
            Bs[r][c] = (n < N) ? Bm[(size_t)(k0 + r) * N + n] : 0.f;
        }
        __syncthreads();
#pragma unroll
        for (int kk = 0; kk < 16; kk++) {
            float4 a4 = *reinterpret_cast<const float4*>(&As[kk][ty * 4]);
            float4 b4 = *reinterpret_cast<const float4*>(&Bs[kk][tx * 4]);
            float a[4] = {a4.x, a4.y, a4.z, a4.w};
            float bv[4] = {b4.x, b4.y, b4.z, b4.w};
#pragma unroll
            for (int i = 0; i < 4; i++)
#pragma unroll
                for (int j = 0; j < 4; j++)
                    acc[i][j] = fmaf(a[i], bv[j], acc[i][j]);
        }
        __syncthreads();
    }
#pragma unroll
    for (int i = 0; i < 4; i++) {
        int m = m0 + ty * 4 + i;
#pragma unroll
        for (int j = 0; j < 4; j++) {
            int n = n0 + tx * 4 + j;
            if (n < N) C[(size_t)m * N + n] = acc[i][j] + bias[n];
        }
    }
}

// ---------------- host orchestration ----------------
extern "C" void kernel_launch(void* const* d_in, const int* in_sizes, int n_in,
                              void* d_out, int out_size) {
    const int*   ids          = (const int*)d_in[0];
    const int*   mul          = (const int*)d_in[1];
    const float* tok_emb      = (const float*)d_in[2];
    const float* state_emb    = (const float*)d_in[3];
    const float* state_proj_w = (const float*)d_in[4];
    const float* state_proj_b = (const float*)d_in[5];
    const float* wpe          = (const float*)d_in[6];
    const float* ln1_g        = (const float*)d_in[7];
    const float* ln1_b        = (const float*)d_in[8];
    const float* attn_w       = (const float*)d_in[9];
    const float* attn_b       = (const float*)d_in[10];
    const float* attn_proj_w  = (const float*)d_in[11];
    const float* attn_proj_b  = (const float*)d_in[12];
    const float* ln2_g        = (const float*)d_in[13];
    const float* ln2_b        = (const float*)d_in[14];
    const float* fc_w         = (const float*)d_in[15];
    const float* fc_b         = (const float*)d_in[16];
    const float* mlp_proj_w   = (const float*)d_in[17];
    const float* mlp_proj_b   = (const float*)d_in[18];
    const float* lnf_g        = (const float*)d_in[19];
    const float* lnf_b        = (const float*)d_in[20];
    const float* head_w       = (const float*)d_in[21];
    const float* head_b       = (const float*)d_in[22];
    float* out = (float*)d_out;

    float *h, *lnbuf, *qkv;
    __half *wh, *lnh, *lnl, *atth, *attl, *midh, *midl;
    cudaGetSymbolAddress((void**)&h,     g_h);
    cudaGetSymbolAddress((void**)&lnbuf, g_ln);
    cudaGetSymbolAddress((void**)&qkv,   g_qkv);
    cudaGetSymbolAddress((void**)&wh,    g_wh);
    cudaGetSymbolAddress((void**)&lnh,   g_lnh);
    cudaGetSymbolAddress((void**)&lnl,   g_lnl);
    cudaGetSymbolAddress((void**)&atth,  g_atth);
    cudaGetSymbolAddress((void**)&attl,  g_attl);
    cudaGetSymbolAddress((void**)&midh,  g_midh);
    cudaGetSymbolAddress((void**)&midl,  g_midl);

    cudaFuncSetAttribute(mma_gemm<0>, cudaFuncAttributeMaxDynamicSharedMemorySize, GEMM_SMEM);
    cudaFuncSetAttribute(mma_gemm<1>, cudaFuncAttributeMaxDynamicSharedMemorySize, GEMM_SMEM);
    cudaFuncSetAttribute(mma_gemm<2>, cudaFuncAttributeMaxDynamicSharedMemorySize, GEMM_SMEM);
    cudaFuncSetAttribute(flash_kernel, cudaFuncAttributeMaxDynamicSharedMemorySize, FL_SMEM);

    wconv_kernel<<<dim3(QKVN/32, EMB/32, NLAYER), 256>>>(attn_w, wh + OFF_QKV, EMB, QKVN);
    wconv_kernel<<<dim3(EMB/32, EMB/32, NLAYER), 256>>>(attn_proj_w, wh + OFF_PROJ, EMB, EMB);
    wconv_kernel<<<dim3(FFN/32, EMB/32, NLAYER), 256>>>(fc_w, wh + OFF_FC, EMB, FFN);
    wconv_kernel<<<dim3(EMB/32, FFN/32, NLAYER), 256>>>(mlp_proj_w, wh + OFF_MLP, FFN, EMB);

    state_scan_kernel<<<1, 256>>>(ids, mul);
    state_proj_kernel<<<(VOC * EMB + 255) / 256, 256>>>(state_emb, state_proj_w, state_proj_b);
    embed_kernel<<<(BT * EMB + 255) / 256, 256>>>(ids, tok_emb, wpe);

    for (int l = 0; l < NLAYER; l++) {
        ln_f16_kernel<<<BT, 256>>>(h, ln1_g + l * EMB, ln1_b + l * EMB, lnh, lnl);
        mma_gemm<0><<<dim3(QKVN/64, BT/128), 256, GEMM_SMEM>>>(
            lnh, lnl, wh + OFF_QKV + (size_t)l * W_QKV,
            attn_b + l * QKVN, nullptr, qkv, nullptr, nullptr, EMB, QKVN);
        flash_kernel<<<dim3(SEQ/128, BATCH * NH), 256, FL_SMEM>>>();
        mma_gemm<1><<<dim3(EMB/64, BT/128), 256, GEMM_SMEM>>>(
            atth, attl, wh + OFF_PROJ + (size_t)l * W_PROJ,
            attn_proj_b + l * EMB, h, h, nullptr, nullptr, EMB, EMB);
        ln_f16_kernel<<<BT, 256>>>(h, ln2_g + l * EMB, ln2_b + l * EMB, lnh, lnl);
        mma_gemm<2><<<dim3(FFN/64, BT/128), 256, GEMM_SMEM>>>(
            lnh, lnl, wh + OFF_FC + (size_t)l * W_FC,
            fc_b + l * FFN, nullptr, nullptr, midh, midl, EMB, FFN);
        mma_gemm<1><<<dim3(EMB/64, BT/128), 256, GEMM_SMEM>>>(
            midh, midl, wh + OFF_MLP + (size_t)l * W_MLP,
            mlp_proj_b + l * EMB, h, h, nullptr, nullptr, FFN, EMB);
    }

    ln_kernel<<<BT, 256>>>(h, lnf_g, lnf_b, lnbuf);
    head_gemm_kernel<<<dim3(1, BT / 64), 256>>>(lnbuf, head_w, head_b, out, VOC, EMB);
}